// round 2
// baseline (speedup 1.0000x reference)
#include <cuda_runtime.h>
#include <cuda_bf16.h>
#include <math.h>

// ---------------- problem constants ----------------
#define BB 64
#define TT 256
#define EE 300
#define EP 304          // padded E
#define HH 256
#define INTER 128
#define NUM_LABELS 17
#define TL 19           // TOTAL_LABELS
#define START_IDX 17
#define END_IDX 18
#define LOW_POT -10000.0f

#define MTOT (BB*TT)            // 16384, m = t*64 + b
#define NB_LSTM 128             // persistent blocks
#define GRP_SZ 16               // blocks per barrier group (dir x batch-chunk)

typedef unsigned long long u64t;

// packed fp32x2 FMA (sm_100+): d = a*b + d elementwise, exact IEEE per lane
__device__ __forceinline__ void ffma2(u64t& d, u64t a, u64t b) {
    asm("fma.rn.f32x2 %0, %1, %2, %0;" : "+l"(d) : "l"(a), "l"(b));
}
__device__ __forceinline__ float2 unpack2(u64t v) {
    float2 r; asm("mov.b64 {%0,%1}, %2;" : "=f"(r.x), "=f"(r.y) : "l"(v)); return r;
}

// ---------------- scratch (device globals; allocation-free rule) ----------------
__device__ float g_emb[MTOT * EP];            // [m][304]
__device__ float g_xproj[(size_t)MTOT * 2048];// [t][b][dir*1024 + g*256 + u]
__device__ float g_hcat[(size_t)MTOT * 512];  // [t][b][dir*256 + u]
__device__ float g_unary[BB * TT * TL];       // [b][t][l]
__device__ unsigned g_cnt[8 * 32];            // per-group barrier counters (padded)
__device__ unsigned g_sense[8 * 32];

// ---------------- embedding gather ----------------
__global__ void k_embed(const int* __restrict__ x, const float* __restrict__ tbl) {
    int idx = blockIdx.x * 256 + threadIdx.x;
    if (idx >= MTOT * EP) return;
    int m = idx / EP, e = idx - m * EP;
    int bat = m & 63, t = m >> 6;
    int tok = x[bat * TT + t];
    g_emb[idx] = (e < EE) ? tbl[(size_t)tok * EE + e] : 0.f;
}

// ---------------- x_proj GEMM: [16384,304] x [304,2048] + bias (f32x2) ----------------
__global__ void k_gemm_xproj(const float* __restrict__ Wf, const float* __restrict__ Wb,
                             const float* __restrict__ bf, const float* __restrict__ bb) {
    __shared__ float2 As2[16][66];   // A duplicated per-element: (a,a); row stride 528B (16B aligned, bank-shifted)
    __shared__ float  Bs[16][68];
    int n0 = blockIdx.x * 64;
    int m0 = blockIdx.y * 64;
    int tid = threadIdx.x;
    int tm = tid >> 4, tn = tid & 15;
    int arow = tid >> 2, aq = tid & 3;

    int ng = n0 + arow;
    const float* Wrow = (ng < 1024) ? (Wf + (size_t)ng * EE) : (Wb + (size_t)(ng - 1024) * EE);

    u64t acc[4][2];
#pragma unroll
    for (int i = 0; i < 4; ++i) { acc[i][0] = 0ull; acc[i][1] = 0ull; }

    for (int kt = 0; kt < 19; ++kt) {
        int k0 = kt * 16;
        float4 av = *(const float4*)(g_emb + (size_t)(m0 + arow) * EP + k0 + aq * 4);
        As2[aq * 4 + 0][arow] = make_float2(av.x, av.x);
        As2[aq * 4 + 1][arow] = make_float2(av.y, av.y);
        As2[aq * 4 + 2][arow] = make_float2(av.z, av.z);
        As2[aq * 4 + 3][arow] = make_float2(av.w, av.w);
#pragma unroll
        for (int j = 0; j < 4; ++j) {
            int kk = k0 + aq * 4 + j;
            Bs[aq * 4 + j][arow] = (kk < EE) ? Wrow[kk] : 0.f;
        }
        __syncthreads();
#pragma unroll
        for (int k = 0; k < 16; ++k) {
            ulonglong2 a01 = *(const ulonglong2*)&As2[k][tm * 4];
            ulonglong2 a23 = *(const ulonglong2*)&As2[k][tm * 4 + 2];
            ulonglong2 b   = *(const ulonglong2*)&Bs[k][tn * 4];
            ffma2(acc[0][0], a01.x, b.x); ffma2(acc[0][1], a01.x, b.y);
            ffma2(acc[1][0], a01.y, b.x); ffma2(acc[1][1], a01.y, b.y);
            ffma2(acc[2][0], a23.x, b.x); ffma2(acc[2][1], a23.x, b.y);
            ffma2(acc[3][0], a23.y, b.x); ffma2(acc[3][1], a23.y, b.y);
        }
        __syncthreads();
    }
    int nbase = n0 + tn * 4;
    float bias[4];
#pragma unroll
    for (int j = 0; j < 4; ++j) {
        int n = nbase + j;
        bias[j] = (n < 1024) ? bf[n] : bb[n - 1024];
    }
#pragma unroll
    for (int i = 0; i < 4; ++i) {
        int m = m0 + tm * 4 + i;
        float2 p0 = unpack2(acc[i][0]);
        float2 p1 = unpack2(acc[i][1]);
        float4 o;
        o.x = p0.x + bias[0];
        o.y = p0.y + bias[1];
        o.z = p1.x + bias[2];
        o.w = p1.y + bias[3];
        *(float4*)(g_xproj + (size_t)m * 2048 + nbase) = o;
    }
}

// ---------------- persistent BiLSTM recurrence ----------------
__device__ __forceinline__ void grp_barrier(int grp, unsigned* ls) {
    __syncthreads();
    if (threadIdx.x == 0) {
        *ls ^= 1u;
        __threadfence();
        unsigned old = atomicAdd(&g_cnt[grp * 32], 1u);
        if (old == GRP_SZ - 1) {
            g_cnt[grp * 32] = 0u;
            __threadfence();
            atomicExch(&g_sense[grp * 32], *ls);
        } else {
            while (*(volatile unsigned*)&g_sense[grp * 32] != *ls) { }
            __threadfence();
        }
    }
    __syncthreads();
}

__device__ __forceinline__ float sigf(float x) { return 1.f / (1.f + expf(-x)); }

// 128 blocks: dir(2) x unit-chunk(16, 16 units each) x batch-chunk(4, 16 rows each)
// thread (lu,lb): owns hidden unit U=uc*16+lu for batch b=bc*16+lb. c-state in register.
__global__ void __launch_bounds__(256, 1) k_lstm(const float* __restrict__ Whh_f,
                                                 const float* __restrict__ Whh_b) {
    extern __shared__ float sm[];
    float4* W4 = (float4*)sm;                 // [kc(64)][lu(16)][g(4)] = 64KB
    float4* h4 = (float4*)(sm + 16384);       // [kc(64)][lb(16)]       = 16KB

    int bx = blockIdx.x;
    int dir = bx >> 6;
    int rem = bx & 63;
    int uc = rem >> 2;
    int bc = rem & 3;
    int grp = dir * 4 + bc;                   // 16 blocks share a group
    int tid = threadIdx.x;
    int lu = tid >> 4;
    int lb = tid & 15;
    int U = uc * 16 + lu;
    int B0 = bc * 16;
    int b = B0 + lb;
    const float* Whh = dir ? Whh_b : Whh_f;

    // load W slice once: rows {g*256+U' : U' in chunk, g in 0..3}
    for (int i = tid; i < 64 * 64; i += 256) {
        int r = i >> 6;        // 0..63 local row
        int kc = i & 63;
        int lur = r >> 2, g = r & 3;
        int grow = g * 256 + uc * 16 + lur;
        W4[(kc * 16 + lur) * 4 + g] = *(const float4*)(Whh + (size_t)grow * HH + kc * 4);
    }

    float c_st = 0.f;
    unsigned ls = 0;

    for (int s = 0; s < TT; ++s) {
        int t = dir ? (TT - 1 - s) : s;
        u64t a_i = 0ull, a_f = 0ull, a_g = 0ull, a_o = 0ull;
        if (s > 0) {
            grp_barrier(grp, &ls);
            int tp = dir ? (t + 1) : (t - 1);
            const float* hp = g_hcat + ((size_t)(tp * 64 + B0)) * 512 + dir * 256;
#pragma unroll
            for (int i = 0; i < 4; ++i) {
                int idx = i * 256 + tid;
                int c4 = idx >> 4;
                int lbi = idx & 15;
                h4[c4 * 16 + lbi] = *(const float4*)(hp + lbi * 512 + c4 * 4);
            }
        }
        __syncthreads();
        if (s > 0) {
#pragma unroll 4
            for (int kc = 0; kc < 64; ++kc) {
                ulonglong2 hv = *(const ulonglong2*)&h4[kc * 16 + lb];
                const ulonglong2* wr = (const ulonglong2*)&W4[(kc * 16 + lu) * 4];
                ulonglong2 wi = wr[0], wf = wr[1], wg = wr[2], wo = wr[3];
                ffma2(a_i, hv.x, wi.x); ffma2(a_i, hv.y, wi.y);
                ffma2(a_f, hv.x, wf.x); ffma2(a_f, hv.y, wf.y);
                ffma2(a_g, hv.x, wg.x); ffma2(a_g, hv.y, wg.y);
                ffma2(a_o, hv.x, wo.x); ffma2(a_o, hv.y, wo.y);
            }
        }
        float2 vi = unpack2(a_i), vf = unpack2(a_f), vg = unpack2(a_g), vo = unpack2(a_o);
        const float* xp = g_xproj + ((size_t)(t * 64 + b)) * 2048 + dir * 1024 + U;
        float pi = vi.x + vi.y + xp[0];
        float pf = vf.x + vf.y + xp[256];
        float pg = vg.x + vg.y + xp[512];
        float po = vo.x + vo.y + xp[768];
        c_st = sigf(pf) * c_st + sigf(pi) * tanhf(pg);
        float h = sigf(po) * tanhf(c_st);
        g_hcat[((size_t)(t * 64 + b)) * 512 + dir * 256 + U] = h;
    }
    grp_barrier(grp, &ls); // restore sense parity for next graph replay
}

// ---------------- fc1 + relu + cls -> unary (fused, f32x2) ----------------
__global__ void k_fc(const float* __restrict__ W1, const float* __restrict__ b1,
                     const float* __restrict__ Wc, const float* __restrict__ bcls) {
    extern __shared__ float sm[];
    float2 (*As2)[66]  = (float2(*)[66])sm;                 // 16*66 float2 = 8448B
    float (*Bs)[132] = (float(*)[132])(sm + 2112);          // 16*132 = 2112 f
    float* cls_sh  = sm + 2112 + 2112;                      // 17*128 = 2176 f
    float* clsb_sh = cls_sh + 2176;                         // 32 f
    float* inter   = clsb_sh + 32;                          // 64*132 = 8448 f

    int m0 = blockIdx.x * 64;
    int tid = threadIdx.x;
    int tm = tid >> 4, tn = tid & 15;
    int arow = tid >> 2, aq = tid & 3;
    int brow = tid >> 1, bq = tid & 1;

    for (int i = tid; i < 17 * 128; i += 256) cls_sh[i] = Wc[i];
    if (tid < 17) clsb_sh[tid] = bcls[tid];

    u64t acc[4][4];
#pragma unroll
    for (int i = 0; i < 4; ++i)
#pragma unroll
        for (int j = 0; j < 4; ++j) acc[i][j] = 0ull;

    for (int kt = 0; kt < 32; ++kt) {
        int k0 = kt * 16;
        float4 av = *(const float4*)(g_hcat + (size_t)(m0 + arow) * 512 + k0 + aq * 4);
        As2[aq * 4 + 0][arow] = make_float2(av.x, av.x);
        As2[aq * 4 + 1][arow] = make_float2(av.y, av.y);
        As2[aq * 4 + 2][arow] = make_float2(av.z, av.z);
        As2[aq * 4 + 3][arow] = make_float2(av.w, av.w);
#pragma unroll
        for (int q = 0; q < 2; ++q) {
            float4 bv = *(const float4*)(W1 + (size_t)brow * 512 + k0 + bq * 8 + q * 4);
            Bs[bq * 8 + q * 4 + 0][brow] = bv.x;
            Bs[bq * 8 + q * 4 + 1][brow] = bv.y;
            Bs[bq * 8 + q * 4 + 2][brow] = bv.z;
            Bs[bq * 8 + q * 4 + 3][brow] = bv.w;
        }
        __syncthreads();
#pragma unroll
        for (int k = 0; k < 16; ++k) {
            ulonglong2 a01 = *(const ulonglong2*)&As2[k][tm * 4];
            ulonglong2 a23 = *(const ulonglong2*)&As2[k][tm * 4 + 2];
            ulonglong2 b03 = *(const ulonglong2*)&Bs[k][tn * 8];
            ulonglong2 b47 = *(const ulonglong2*)&Bs[k][tn * 8 + 4];
            ffma2(acc[0][0], a01.x, b03.x); ffma2(acc[0][1], a01.x, b03.y);
            ffma2(acc[0][2], a01.x, b47.x); ffma2(acc[0][3], a01.x, b47.y);
            ffma2(acc[1][0], a01.y, b03.x); ffma2(acc[1][1], a01.y, b03.y);
            ffma2(acc[1][2], a01.y, b47.x); ffma2(acc[1][3], a01.y, b47.y);
            ffma2(acc[2][0], a23.x, b03.x); ffma2(acc[2][1], a23.x, b03.y);
            ffma2(acc[2][2], a23.x, b47.x); ffma2(acc[2][3], a23.x, b47.y);
            ffma2(acc[3][0], a23.y, b03.x); ffma2(acc[3][1], a23.y, b03.y);
            ffma2(acc[3][2], a23.y, b47.x); ffma2(acc[3][3], a23.y, b47.y);
        }
        __syncthreads();
    }
    // bias + relu -> inter smem
#pragma unroll
    for (int i = 0; i < 4; ++i) {
        int ml = tm * 4 + i;
#pragma unroll
        for (int j = 0; j < 4; ++j) {
            float2 p = unpack2(acc[i][j]);
            int n = tn * 8 + j * 2;
            float v0 = p.x + b1[n];
            float v1 = p.y + b1[n + 1];
            inter[ml * 132 + n]     = v0 > 0.f ? v0 : 0.f;
            inter[ml * 132 + n + 1] = v1 > 0.f ? v1 : 0.f;
        }
    }
    __syncthreads();
    // second GEMM: 64 x 17 (plus LOW_POT pad to 19), f32x2 over k
    for (int o = tid; o < 64 * TL; o += 256) {
        int ml = o / TL, l = o - ml * TL;
        int m = m0 + ml;
        int t = m >> 6, bat = m & 63;
        float v;
        if (l < NUM_LABELS) {
            u64t s2 = 0ull;
            const ulonglong2* ip = (const ulonglong2*)(inter + ml * 132);
            const ulonglong2* cp = (const ulonglong2*)(cls_sh + l * 128);
#pragma unroll 8
            for (int k4 = 0; k4 < 32; ++k4) {
                ulonglong2 a = ip[k4], c = cp[k4];
                ffma2(s2, a.x, c.x);
                ffma2(s2, a.y, c.y);
            }
            float2 p = unpack2(s2);
            v = clsb_sh[l] + p.x + p.y;
        } else {
            v = LOW_POT;
        }
        g_unary[((size_t)bat * TT + t) * TL + l] = v;
    }
}

// ---------------- Viterbi: one warp per batch element ----------------
__global__ void k_viterbi(const float* __restrict__ trans, float* __restrict__ out,
                          int score_off, int labels_off) {
    __shared__ float tr[TL * TL];
    __shared__ unsigned char bp[TT * TL];
    int b = blockIdx.x;
    int l = threadIdx.x;

    for (int i = l; i < TL * TL; i += 32) tr[i] = trans[i];
    __syncwarp();

    float score = (l == START_IDX) ? 0.f : LOW_POT;
    const float* ub = g_unary + (size_t)b * TT * TL;

    for (int t = 0; t < TT; ++t) {
        float u = (l < TL) ? ub[t * TL + l] : LOW_POT;
        float best = -3.4e38f;
        int bi = 0;
#pragma unroll
        for (int p = 0; p < TL; ++p) {
            float sp = __shfl_sync(0xffffffffu, score, p);
            float cnd = sp + ((l < TL) ? tr[l * TL + p] : 0.f);
            if (cnd > best) { best = cnd; bi = p; }   // strict > => first max (matches jnp.argmax)
        }
        score = best + u;
        if (l < TL) bp[t * TL + l] = (unsigned char)bi;
        __syncwarp();
    }
    float fin = (l < TL) ? (score + tr[END_IDX * TL + l]) : -3.4e38f;
    int idx = (l < TL) ? l : 31;
#pragma unroll
    for (int off = 16; off; off >>= 1) {
        float ov = __shfl_down_sync(0xffffffffu, fin, off);
        int   oi = __shfl_down_sync(0xffffffffu, idx, off);
        if (ov > fin || (ov == fin && oi < idx)) { fin = ov; idx = oi; }
    }
    if (l == 0) {
        if (score_off >= 0) out[score_off + b] = fin;
        if (labels_off >= 0) {
            int lab = idx;
            float* lo = out + labels_off + (size_t)b * TT;
            lo[TT - 1] = (float)lab;
            for (int t = TT - 1; t >= 1; --t) {
                lab = bp[t * TL + lab];
                lo[t - 1] = (float)lab;
            }
        }
    }
}

// ---------------- launch ----------------
extern "C" void kernel_launch(void* const* d_in, const int* in_sizes, int n_in,
                              void* d_out, int out_size) {
    const int*   x        = (const int*)d_in[0];
    const float* emb_tab  = (const float*)d_in[1];
    const float* W_ih_f   = (const float*)d_in[2];
    const float* W_hh_f   = (const float*)d_in[3];
    const float* b_f      = (const float*)d_in[4];
    const float* W_ih_b   = (const float*)d_in[5];
    const float* W_hh_b   = (const float*)d_in[6];
    const float* b_b      = (const float*)d_in[7];
    const float* fc1_W    = (const float*)d_in[8];
    const float* fc1_b    = (const float*)d_in[9];
    const float* cls_W    = (const float*)d_in[10];
    const float* cls_b    = (const float*)d_in[11];
    const float* trans    = (const float*)d_in[12];
    float* out = (float*)d_out;

    cudaFuncSetAttribute(k_lstm, cudaFuncAttributeMaxDynamicSharedMemorySize, 81920);
    cudaFuncSetAttribute(k_fc,   cudaFuncAttributeMaxDynamicSharedMemorySize, 65536);

    k_embed<<<(MTOT * EP + 255) / 256, 256>>>(x, emb_tab);

    dim3 g1(2048 / 64, MTOT / 64);
    k_gemm_xproj<<<g1, 256>>>(W_ih_f, W_ih_b, b_f, b_b);

    k_lstm<<<NB_LSTM, 256, 81920>>>(W_hh_f, W_hh_b);

    k_fc<<<MTOT / 64, 256, 65536>>>(fc1_W, fc1_b, cls_W, cls_b);

    int score_off, labels_off;
    if (out_size >= BB + BB * TT) { score_off = 0; labels_off = BB; }
    else if (out_size == BB * TT) { score_off = -1; labels_off = 0; }
    else                          { score_off = 0; labels_off = -1; }
    k_viterbi<<<BB, 32>>>(trans, out, score_off, labels_off);
}

// round 9
// speedup vs baseline: 1.1583x; 1.1583x over previous
#include <cuda_runtime.h>
#include <cuda_bf16.h>
#include <math.h>

// ---------------- problem constants ----------------
#define BB 64
#define TT 256
#define EE 300
#define HH 256
#define INTER 128
#define NUM_LABELS 17
#define TL 19           // TOTAL_LABELS
#define START_IDX 17
#define END_IDX 18
#define LOW_POT -10000.0f

#define MTOT (BB*TT)            // 16384, m = t*64 + b
#define NB_LSTM 128             // persistent blocks
#define GRP_SZ 16               // blocks per barrier group (dir x batch-chunk)

typedef unsigned long long u64t;

// packed fp32x2 FMA (sm_100+): d = a*b + d elementwise, exact IEEE per lane
__device__ __forceinline__ void ffma2(u64t& d, u64t a, u64t b) {
    asm("fma.rn.f32x2 %0, %1, %2, %0;" : "+l"(d) : "l"(a), "l"(b));
}
__device__ __forceinline__ u64t pack2(float lo, float hi) {
    u64t r; asm("mov.b64 %0, {%1,%2};" : "=l"(r) : "f"(lo), "f"(hi)); return r;
}
__device__ __forceinline__ float2 unpack2(u64t v) {
    float2 r; asm("mov.b64 {%0,%1}, %2;" : "=f"(r.x), "=f"(r.y) : "l"(v)); return r;
}

// ---------------- scratch (device globals; allocation-free rule) ----------------
__device__ float g_xproj[(size_t)MTOT * 2048];// [t][b][dir*1024 + g*256 + u]
__device__ float g_hcat[(size_t)MTOT * 512];  // [t][b][dir*256 + u]
__device__ float g_unary[BB * TT * TL];       // [b][t][l]
__device__ unsigned g_cnt[8 * 32];            // per-group barrier counters (padded)
__device__ unsigned g_sense[8 * 32];

// ---------------- x_proj GEMM (fused embedding gather) ----------------
// C[16384, 2048] = emb[x][.] (K=300) x W^T + bias. 128x128 tile, 8x8/thread, f32x2 m-paired.
__global__ void __launch_bounds__(256) k_gemm_xproj(
        const int* __restrict__ x, const float* __restrict__ emb,
        const float* __restrict__ Wf, const float* __restrict__ Wb,
        const float* __restrict__ bf, const float* __restrict__ bb) {
    __shared__ float As[16][132];   // [k][m] transposed
    __shared__ float Bs[16][132];   // [k][n] transposed
    int tid = threadIdx.x;
    int n0 = blockIdx.x * 128;
    int m0 = blockIdx.y * 128;
    int tx = tid & 15, ty = tid >> 4;
    int lrow = tid >> 2;          // 0..63
    int kq = (tid & 3) * 4;       // 0,4,8,12

    // per-thread sources for the 2 A rows and 2 B rows it stages
    int tok[2]; const float* wsrc[2];
#pragma unroll
    for (int it = 0; it < 2; ++it) {
        int m = m0 + lrow + it * 64;
        tok[it] = x[(m & 63) * TT + (m >> 6)];
        int ng = n0 + lrow + it * 64;
        wsrc[it] = (ng < 1024) ? (Wf + (size_t)ng * EE) : (Wb + (size_t)(ng - 1024) * EE);
    }

    u64t acc[4][8];
#pragma unroll
    for (int i = 0; i < 4; ++i)
#pragma unroll
        for (int j = 0; j < 8; ++j) acc[i][j] = 0ull;

    for (int kt = 0; kt < 19; ++kt) {
        int kb = kt * 16 + kq;
#pragma unroll
        for (int it = 0; it < 2; ++it) {
            float4 av = make_float4(0.f, 0.f, 0.f, 0.f);
            float4 bv = make_float4(0.f, 0.f, 0.f, 0.f);
            if (kb < EE) {   // EE=300, kb%4==0, rows 16B aligned -> safe float4
                av = *(const float4*)(emb + (size_t)tok[it] * EE + kb);
                bv = *(const float4*)(wsrc[it] + kb);
            }
            int r = lrow + it * 64;
            As[kq + 0][r] = av.x; As[kq + 1][r] = av.y; As[kq + 2][r] = av.z; As[kq + 3][r] = av.w;
            Bs[kq + 0][r] = bv.x; Bs[kq + 1][r] = bv.y; Bs[kq + 2][r] = bv.z; Bs[kq + 3][r] = bv.w;
        }
        __syncthreads();
#pragma unroll
        for (int k = 0; k < 16; ++k) {
            ulonglong2 aA = *(const ulonglong2*)&As[k][ty * 8];      // m-pairs 0,1
            ulonglong2 aB = *(const ulonglong2*)&As[k][ty * 8 + 4];  // m-pairs 2,3
            float4 b0 = *(const float4*)&Bs[k][tx * 8];
            float4 b1 = *(const float4*)&Bs[k][tx * 8 + 4];
            u64t bd;
            bd = pack2(b0.x, b0.x); ffma2(acc[0][0], aA.x, bd); ffma2(acc[1][0], aA.y, bd); ffma2(acc[2][0], aB.x, bd); ffma2(acc[3][0], aB.y, bd);
            bd = pack2(b0.y, b0.y); ffma2(acc[0][1], aA.x, bd); ffma2(acc[1][1], aA.y, bd); ffma2(acc[2][1], aB.x, bd); ffma2(acc[3][1], aB.y, bd);
            bd = pack2(b0.z, b0.z); ffma2(acc[0][2], aA.x, bd); ffma2(acc[1][2], aA.y, bd); ffma2(acc[2][2], aB.x, bd); ffma2(acc[3][2], aB.y, bd);
            bd = pack2(b0.w, b0.w); ffma2(acc[0][3], aA.x, bd); ffma2(acc[1][3], aA.y, bd); ffma2(acc[2][3], aB.x, bd); ffma2(acc[3][3], aB.y, bd);
            bd = pack2(b1.x, b1.x); ffma2(acc[0][4], aA.x, bd); ffma2(acc[1][4], aA.y, bd); ffma2(acc[2][4], aB.x, bd); ffma2(acc[3][4], aB.y, bd);
            bd = pack2(b1.y, b1.y); ffma2(acc[0][5], aA.x, bd); ffma2(acc[1][5], aA.y, bd); ffma2(acc[2][5], aB.x, bd); ffma2(acc[3][5], aB.y, bd);
            bd = pack2(b1.z, b1.z); ffma2(acc[0][6], aA.x, bd); ffma2(acc[1][6], aA.y, bd); ffma2(acc[2][6], aB.x, bd); ffma2(acc[3][6], aB.y, bd);
            bd = pack2(b1.w, b1.w); ffma2(acc[0][7], aA.x, bd); ffma2(acc[1][7], aA.y, bd); ffma2(acc[2][7], aB.x, bd); ffma2(acc[3][7], aB.y, bd);
        }
        __syncthreads();
    }
    // bias for the 8 n columns
    float bias[8];
#pragma unroll
    for (int j = 0; j < 8; ++j) {
        int n = n0 + tx * 8 + j;
        bias[j] = (n < 1024) ? bf[n] : bb[n - 1024];
    }
#pragma unroll
    for (int r = 0; r < 8; ++r) {
        int m = m0 + ty * 8 + r;
        int mp = r >> 1, hi = r & 1;
        float v[8];
#pragma unroll
        for (int j = 0; j < 8; ++j) {
            float2 p = unpack2(acc[mp][j]);
            v[j] = (hi ? p.y : p.x) + bias[j];
        }
        float* cp = g_xproj + (size_t)m * 2048 + n0 + tx * 8;
        *(float4*)cp       = make_float4(v[0], v[1], v[2], v[3]);
        *(float4*)(cp + 4) = make_float4(v[4], v[5], v[6], v[7]);
    }
}

// ---------------- persistent BiLSTM recurrence ----------------
__device__ __forceinline__ void grp_barrier(int grp, unsigned* ls) {
    __syncthreads();
    if (threadIdx.x == 0) {
        *ls ^= 1u;
        __threadfence();
        unsigned old = atomicAdd(&g_cnt[grp * 32], 1u);
        if (old == GRP_SZ - 1) {
            g_cnt[grp * 32] = 0u;
            __threadfence();
            atomicExch(&g_sense[grp * 32], *ls);
        } else {
            while (*(volatile unsigned*)&g_sense[grp * 32] != *ls) { }
            __threadfence();
        }
    }
    __syncthreads();
}

__device__ __forceinline__ float sigf(float x) { return 1.f / (1.f + expf(-x)); }

// 128 blocks: dir(2) x unit-chunk(16, 16 units each) x batch-chunk(4, 16 rows each)
__global__ void __launch_bounds__(256, 1) k_lstm(const float* __restrict__ Whh_f,
                                                 const float* __restrict__ Whh_b) {
    extern __shared__ float sm[];
    float4* W4 = (float4*)sm;                 // [kc(64)][lu(16)][g(4)] = 64KB
    float4* h4 = (float4*)(sm + 16384);       // [kc(64)][lb(16)]       = 16KB

    int bx = blockIdx.x;
    int dir = bx >> 6;
    int rem = bx & 63;
    int uc = rem >> 2;
    int bc = rem & 3;
    int grp = dir * 4 + bc;
    int tid = threadIdx.x;
    int lu = tid >> 4;
    int lb = tid & 15;
    int U = uc * 16 + lu;
    int B0 = bc * 16;
    int b = B0 + lb;
    const float* Whh = dir ? Whh_b : Whh_f;

    for (int i = tid; i < 64 * 64; i += 256) {
        int r = i >> 6;
        int kc = i & 63;
        int lur = r >> 2, g = r & 3;
        int grow = g * 256 + uc * 16 + lur;
        W4[(kc * 16 + lur) * 4 + g] = *(const float4*)(Whh + (size_t)grow * HH + kc * 4);
    }

    float c_st = 0.f;
    unsigned ls = 0;

    for (int s = 0; s < TT; ++s) {
        int t = dir ? (TT - 1 - s) : s;
        // prefetch gate pre-activations BEFORE the barrier (independent of h)
        const float* xp = g_xproj + ((size_t)(t * 64 + b)) * 2048 + dir * 1024 + U;
        float x_i = xp[0];
        float x_f = xp[256];
        float x_g = xp[512];
        float x_o = xp[768];

        u64t a_i = 0ull, a_f = 0ull, a_g = 0ull, a_o = 0ull;
        if (s > 0) {
            grp_barrier(grp, &ls);
            int tp = dir ? (t + 1) : (t - 1);
            const float* hp = g_hcat + ((size_t)(tp * 64 + B0)) * 512 + dir * 256;
#pragma unroll
            for (int i = 0; i < 4; ++i) {
                int idx = i * 256 + tid;
                int c4 = idx >> 4;
                int lbi = idx & 15;
                h4[c4 * 16 + lbi] = *(const float4*)(hp + lbi * 512 + c4 * 4);
            }
        }
        __syncthreads();
        if (s > 0) {
#pragma unroll 4
            for (int kc = 0; kc < 64; ++kc) {
                ulonglong2 hv = *(const ulonglong2*)&h4[kc * 16 + lb];
                const ulonglong2* wr = (const ulonglong2*)&W4[(kc * 16 + lu) * 4];
                ulonglong2 wi = wr[0], wf = wr[1], wg = wr[2], wo = wr[3];
                ffma2(a_i, hv.x, wi.x); ffma2(a_i, hv.y, wi.y);
                ffma2(a_f, hv.x, wf.x); ffma2(a_f, hv.y, wf.y);
                ffma2(a_g, hv.x, wg.x); ffma2(a_g, hv.y, wg.y);
                ffma2(a_o, hv.x, wo.x); ffma2(a_o, hv.y, wo.y);
            }
        }
        float2 vi = unpack2(a_i), vf = unpack2(a_f), vg = unpack2(a_g), vo = unpack2(a_o);
        float pi = vi.x + vi.y + x_i;
        float pf = vf.x + vf.y + x_f;
        float pg = vg.x + vg.y + x_g;
        float po = vo.x + vo.y + x_o;
        c_st = sigf(pf) * c_st + sigf(pi) * tanhf(pg);
        float h = sigf(po) * tanhf(c_st);
        g_hcat[((size_t)(t * 64 + b)) * 512 + dir * 256 + U] = h;
    }
    grp_barrier(grp, &ls); // restore sense parity for next graph replay
}

// ---------------- fc1 + relu + cls -> unary (fused, f32x2 m-paired) ----------------
__global__ void k_fc(const float* __restrict__ W1, const float* __restrict__ b1,
                     const float* __restrict__ Wc, const float* __restrict__ bcls) {
    extern __shared__ float sm[];
    float (*As)[68]  = (float(*)[68])sm;                    // [k][m] 16*68 = 1088 f
    float (*Bs)[132] = (float(*)[132])(sm + 1088);          // [k][n] 16*132 = 2112 f
    float* cls_sh  = sm + 1088 + 2112;                      // 17*128 = 2176 f
    float* clsb_sh = cls_sh + 2176;                         // 32 f
    float* inter   = clsb_sh + 32;                          // 64*132 = 8448 f

    int m0 = blockIdx.x * 64;
    int tid = threadIdx.x;
    int tm = tid >> 4, tn = tid & 15;
    int arow = tid >> 2, aq = (tid & 3) * 4;
    int brow = tid >> 1, bq = tid & 1;

    for (int i = tid; i < 17 * 128; i += 256) cls_sh[i] = Wc[i];
    if (tid < 17) clsb_sh[tid] = bcls[tid];

    u64t acc[2][8];
#pragma unroll
    for (int i = 0; i < 2; ++i)
#pragma unroll
        for (int j = 0; j < 8; ++j) acc[i][j] = 0ull;

    for (int kt = 0; kt < 32; ++kt) {
        int k0 = kt * 16;
        float4 av = *(const float4*)(g_hcat + (size_t)(m0 + arow) * 512 + k0 + aq);
        As[aq + 0][arow] = av.x;
        As[aq + 1][arow] = av.y;
        As[aq + 2][arow] = av.z;
        As[aq + 3][arow] = av.w;
#pragma unroll
        for (int q = 0; q < 2; ++q) {
            float4 bv = *(const float4*)(W1 + (size_t)brow * 512 + k0 + bq * 8 + q * 4);
            Bs[bq * 8 + q * 4 + 0][brow] = bv.x;
            Bs[bq * 8 + q * 4 + 1][brow] = bv.y;
            Bs[bq * 8 + q * 4 + 2][brow] = bv.z;
            Bs[bq * 8 + q * 4 + 3][brow] = bv.w;
        }
        __syncthreads();
#pragma unroll
        for (int k = 0; k < 16; ++k) {
            ulonglong2 aA = *(const ulonglong2*)&As[k][tm * 4];  // 2 m-pairs
            float4 b0 = *(const float4*)&Bs[k][tn * 8];
            float4 b1 = *(const float4*)&Bs[k][tn * 8 + 4];
            u64t bd;
            bd = pack2(b0.x, b0.x); ffma2(acc[0][0], aA.x, bd); ffma2(acc[1][0], aA.y, bd);
            bd = pack2(b0.y, b0.y); ffma2(acc[0][1], aA.x, bd); ffma2(acc[1][1], aA.y, bd);
            bd = pack2(b0.z, b0.z); ffma2(acc[0][2], aA.x, bd); ffma2(acc[1][2], aA.y, bd);
            bd = pack2(b0.w, b0.w); ffma2(acc[0][3], aA.x, bd); ffma2(acc[1][3], aA.y, bd);
            bd = pack2(b1.x, b1.x); ffma2(acc[0][4], aA.x, bd); ffma2(acc[1][4], aA.y, bd);
            bd = pack2(b1.y, b1.y); ffma2(acc[0][5], aA.x, bd); ffma2(acc[1][5], aA.y, bd);
            bd = pack2(b1.z, b1.z); ffma2(acc[0][6], aA.x, bd); ffma2(acc[1][6], aA.y, bd);
            bd = pack2(b1.w, b1.w); ffma2(acc[0][7], aA.x, bd); ffma2(acc[1][7], aA.y, bd);
        }
        __syncthreads();
    }
    // bias + relu -> inter smem
#pragma unroll
    for (int r = 0; r < 4; ++r) {
        int ml = tm * 4 + r;
        int mp = r >> 1, hi = r & 1;
#pragma unroll
        for (int j = 0; j < 8; ++j) {
            float2 p = unpack2(acc[mp][j]);
            int n = tn * 8 + j;
            float v = (hi ? p.y : p.x) + b1[n];
            inter[ml * 132 + n] = v > 0.f ? v : 0.f;
        }
    }
    __syncthreads();
    // second GEMM: 64 x 17 (plus LOW_POT pad to 19), f32x2 over k
    for (int o = tid; o < 64 * TL; o += 256) {
        int ml = o / TL, l = o - ml * TL;
        int m = m0 + ml;
        int t = m >> 6, bat = m & 63;
        float v;
        if (l < NUM_LABELS) {
            u64t s2 = 0ull;
            const ulonglong2* ip = (const ulonglong2*)(inter + ml * 132);
            const ulonglong2* cp = (const ulonglong2*)(cls_sh + l * 128);
#pragma unroll 8
            for (int k4 = 0; k4 < 32; ++k4) {
                ulonglong2 a = ip[k4], c = cp[k4];
                ffma2(s2, a.x, c.x);
                ffma2(s2, a.y, c.y);
            }
            float2 p = unpack2(s2);
            v = clsb_sh[l] + p.x + p.y;
        } else {
            v = LOW_POT;
        }
        g_unary[((size_t)bat * TT + t) * TL + l] = v;
    }
}

// ---------------- Viterbi: one warp per batch element ----------------
__global__ void k_viterbi(const float* __restrict__ trans, float* __restrict__ out,
                          int score_off, int labels_off) {
    __shared__ float tr[TL * TL];
    __shared__ unsigned char bp[TT * TL];
    int b = blockIdx.x;
    int l = threadIdx.x;

    for (int i = l; i < TL * TL; i += 32) tr[i] = trans[i];
    __syncwarp();

    float score = (l == START_IDX) ? 0.f : LOW_POT;
    const float* ub = g_unary + (size_t)b * TT * TL;

    for (int t = 0; t < TT; ++t) {
        float u = (l < TL) ? ub[t * TL + l] : LOW_POT;
        float best = -3.4e38f;
        int bi = 0;
#pragma unroll
        for (int p = 0; p < TL; ++p) {
            float sp = __shfl_sync(0xffffffffu, score, p);
            float cnd = sp + ((l < TL) ? tr[l * TL + p] : 0.f);
            if (cnd > best) { best = cnd; bi = p; }
        }
        score = best + u;
        if (l < TL) bp[t * TL + l] = (unsigned char)bi;
        __syncwarp();
    }
    float fin = (l < TL) ? (score + tr[END_IDX * TL + l]) : -3.4e38f;
    int idx = (l < TL) ? l : 31;
#pragma unroll
    for (int off = 16; off; off >>= 1) {
        float ov = __shfl_down_sync(0xffffffffu, fin, off);
        int   oi = __shfl_down_sync(0xffffffffu, idx, off);
        if (ov > fin || (ov == fin && oi < idx)) { fin = ov; idx = oi; }
    }
    if (l == 0) {
        if (score_off >= 0) out[score_off + b] = fin;
        if (labels_off >= 0) {
            int lab = idx;
            float* lo = out + labels_off + (size_t)b * TT;
            lo[TT - 1] = (float)lab;
            for (int t = TT - 1; t >= 1; --t) {
                lab = bp[t * TL + lab];
                lo[t - 1] = (float)lab;
            }
        }
    }
}

// ---------------- launch ----------------
extern "C" void kernel_launch(void* const* d_in, const int* in_sizes, int n_in,
                              void* d_out, int out_size) {
    const int*   x        = (const int*)d_in[0];
    const float* emb_tab  = (const float*)d_in[1];
    const float* W_ih_f   = (const float*)d_in[2];
    const float* W_hh_f   = (const float*)d_in[3];
    const float* b_f      = (const float*)d_in[4];
    const float* W_ih_b   = (const float*)d_in[5];
    const float* W_hh_b   = (const float*)d_in[6];
    const float* b_b      = (const float*)d_in[7];
    const float* fc1_W    = (const float*)d_in[8];
    const float* fc1_b    = (const float*)d_in[9];
    const float* cls_W    = (const float*)d_in[10];
    const float* cls_b    = (const float*)d_in[11];
    const float* trans    = (const float*)d_in[12];
    float* out = (float*)d_out;

    cudaFuncSetAttribute(k_lstm, cudaFuncAttributeMaxDynamicSharedMemorySize, 81920);
    cudaFuncSetAttribute(k_fc,   cudaFuncAttributeMaxDynamicSharedMemorySize, 57344);

    dim3 g1(2048 / 128, MTOT / 128);
    k_gemm_xproj<<<g1, 256>>>(x, emb_tab, W_ih_f, W_ih_b, b_f, b_b);

    k_lstm<<<NB_LSTM, 256, 81920>>>(W_hh_f, W_hh_b);

    k_fc<<<MTOT / 64, 256, 57344>>>(fc1_W, fc1_b, cls_W, cls_b);

    int score_off, labels_off;
    if (out_size >= BB + BB * TT) { score_off = 0; labels_off = BB; }
    else if (out_size == BB * TT) { score_off = -1; labels_off = 0; }
    else                          { score_off = 0; labels_off = -1; }
    k_viterbi<<<BB, 32>>>(trans, out, score_off, labels_off);
}

// round 13
// speedup vs baseline: 1.1657x; 1.0064x over previous
#include <cuda_runtime.h>
#include <cuda_bf16.h>
#include <math.h>

// ---------------- problem constants ----------------
#define BB 64
#define TT 256
#define EE 300
#define HH 256
#define INTER 128
#define NUM_LABELS 17
#define TL 19           // TOTAL_LABELS
#define START_IDX 17
#define END_IDX 18
#define LOW_POT -10000.0f

#define MTOT (BB*TT)            // 16384, m = t*64 + b
#define NB_LSTM 128             // persistent blocks
#define GRP_SZ 16               // blocks per barrier group (dir x batch-chunk)

typedef unsigned long long u64t;

// packed fp32x2 FMA (sm_100+): d = a*b + d elementwise, exact IEEE per lane
__device__ __forceinline__ void ffma2(u64t& d, u64t a, u64t b) {
    asm("fma.rn.f32x2 %0, %1, %2, %0;" : "+l"(d) : "l"(a), "l"(b));
}
__device__ __forceinline__ u64t pack2(float lo, float hi) {
    u64t r; asm("mov.b64 %0, {%1,%2};" : "=l"(r) : "f"(lo), "f"(hi)); return r;
}
__device__ __forceinline__ float2 unpack2(u64t v) {
    float2 r; asm("mov.b64 {%0,%1}, %2;" : "=f"(r.x), "=f"(r.y) : "l"(v)); return r;
}

// ---------------- scratch (device globals; allocation-free rule) ----------------
__device__ float g_xproj[(size_t)MTOT * 2048];// [t][b][dir*1024 + g*256 + u]
__device__ float g_hcat[(size_t)MTOT * 512];  // [t][b][dir*256 + u]
__device__ float g_unary[BB * TT * TL];       // [b][t][l]
__device__ unsigned g_cnt[8 * 32];            // per-group barrier counters (padded)
__device__ unsigned g_sense[8 * 32];

// ---------------- x_proj GEMM (fused embedding gather, double-buffered) ----------------
// C[16384, 2048] = emb[x][.] (K=300) x W^T + bias. 128x128 tile, 8x8/thread, f32x2 m-paired.
__global__ void __launch_bounds__(256) k_gemm_xproj(
        const int* __restrict__ x, const float* __restrict__ emb,
        const float* __restrict__ Wf, const float* __restrict__ Wb,
        const float* __restrict__ bf, const float* __restrict__ bb) {
    __shared__ float As[2][16][132];   // [buf][k][m] transposed
    __shared__ float Bs[2][16][132];   // [buf][k][n] transposed
    int tid = threadIdx.x;
    int n0 = blockIdx.x * 128;
    int m0 = blockIdx.y * 128;
    int tx = tid & 15, ty = tid >> 4;
    int lrow = tid >> 2;          // 0..63
    int kq = (tid & 3) * 4;       // 0,4,8,12

    // per-thread sources for the 2 A rows and 2 B rows it stages
    int tok[2]; const float* wsrc[2];
#pragma unroll
    for (int it = 0; it < 2; ++it) {
        int m = m0 + lrow + it * 64;
        tok[it] = x[(m & 63) * TT + (m >> 6)];
        int ng = n0 + lrow + it * 64;
        wsrc[it] = (ng < 1024) ? (Wf + (size_t)ng * EE) : (Wb + (size_t)(ng - 1024) * EE);
    }

    u64t acc[4][8];
#pragma unroll
    for (int i = 0; i < 4; ++i)
#pragma unroll
        for (int j = 0; j < 8; ++j) acc[i][j] = 0ull;

    // prologue: load tile 0 -> regs -> buf 0
    float4 avr[2], bvr[2];
#pragma unroll
    for (int it = 0; it < 2; ++it) {
        avr[it] = make_float4(0.f, 0.f, 0.f, 0.f);
        bvr[it] = make_float4(0.f, 0.f, 0.f, 0.f);
        if (kq < EE) {
            avr[it] = *(const float4*)(emb + (size_t)tok[it] * EE + kq);
            bvr[it] = *(const float4*)(wsrc[it] + kq);
        }
    }
#pragma unroll
    for (int it = 0; it < 2; ++it) {
        int r = lrow + it * 64;
        As[0][kq + 0][r] = avr[it].x; As[0][kq + 1][r] = avr[it].y;
        As[0][kq + 2][r] = avr[it].z; As[0][kq + 3][r] = avr[it].w;
        Bs[0][kq + 0][r] = bvr[it].x; Bs[0][kq + 1][r] = bvr[it].y;
        Bs[0][kq + 2][r] = bvr[it].z; Bs[0][kq + 3][r] = bvr[it].w;
    }
    __syncthreads();

    for (int kt = 0; kt < 19; ++kt) {
        int cur = kt & 1;
        // prefetch tile kt+1 into registers (LDG latency hidden by compute below)
        if (kt + 1 < 19) {
            int kb = (kt + 1) * 16 + kq;
#pragma unroll
            for (int it = 0; it < 2; ++it) {
                avr[it] = make_float4(0.f, 0.f, 0.f, 0.f);
                bvr[it] = make_float4(0.f, 0.f, 0.f, 0.f);
                if (kb < EE) {   // EE=300, kb%4==0, rows 16B aligned -> safe float4
                    avr[it] = *(const float4*)(emb + (size_t)tok[it] * EE + kb);
                    bvr[it] = *(const float4*)(wsrc[it] + kb);
                }
            }
        }
        // compute on current buffer
#pragma unroll
        for (int k = 0; k < 16; ++k) {
            ulonglong2 aA = *(const ulonglong2*)&As[cur][k][ty * 8];      // m-pairs 0,1
            ulonglong2 aB = *(const ulonglong2*)&As[cur][k][ty * 8 + 4];  // m-pairs 2,3
            float4 b0 = *(const float4*)&Bs[cur][k][tx * 8];
            float4 b1 = *(const float4*)&Bs[cur][k][tx * 8 + 4];
            u64t bd;
            bd = pack2(b0.x, b0.x); ffma2(acc[0][0], aA.x, bd); ffma2(acc[1][0], aA.y, bd); ffma2(acc[2][0], aB.x, bd); ffma2(acc[3][0], aB.y, bd);
            bd = pack2(b0.y, b0.y); ffma2(acc[0][1], aA.x, bd); ffma2(acc[1][1], aA.y, bd); ffma2(acc[2][1], aB.x, bd); ffma2(acc[3][1], aB.y, bd);
            bd = pack2(b0.z, b0.z); ffma2(acc[0][2], aA.x, bd); ffma2(acc[1][2], aA.y, bd); ffma2(acc[2][2], aB.x, bd); ffma2(acc[3][2], aB.y, bd);
            bd = pack2(b0.w, b0.w); ffma2(acc[0][3], aA.x, bd); ffma2(acc[1][3], aA.y, bd); ffma2(acc[2][3], aB.x, bd); ffma2(acc[3][3], aB.y, bd);
            bd = pack2(b1.x, b1.x); ffma2(acc[0][4], aA.x, bd); ffma2(acc[1][4], aA.y, bd); ffma2(acc[2][4], aB.x, bd); ffma2(acc[3][4], aB.y, bd);
            bd = pack2(b1.y, b1.y); ffma2(acc[0][5], aA.x, bd); ffma2(acc[1][5], aA.y, bd); ffma2(acc[2][5], aB.x, bd); ffma2(acc[3][5], aB.y, bd);
            bd = pack2(b1.z, b1.z); ffma2(acc[0][6], aA.x, bd); ffma2(acc[1][6], aA.y, bd); ffma2(acc[2][6], aB.x, bd); ffma2(acc[3][6], aB.y, bd);
            bd = pack2(b1.w, b1.w); ffma2(acc[0][7], aA.x, bd); ffma2(acc[1][7], aA.y, bd); ffma2(acc[2][7], aB.x, bd); ffma2(acc[3][7], aB.y, bd);
        }
        // stage prefetched tile into the other buffer (safe: last sync retired its readers)
        if (kt + 1 < 19) {
            int nxt = cur ^ 1;
#pragma unroll
            for (int it = 0; it < 2; ++it) {
                int r = lrow + it * 64;
                As[nxt][kq + 0][r] = avr[it].x; As[nxt][kq + 1][r] = avr[it].y;
                As[nxt][kq + 2][r] = avr[it].z; As[nxt][kq + 3][r] = avr[it].w;
                Bs[nxt][kq + 0][r] = bvr[it].x; Bs[nxt][kq + 1][r] = bvr[it].y;
                Bs[nxt][kq + 2][r] = bvr[it].z; Bs[nxt][kq + 3][r] = bvr[it].w;
            }
            __syncthreads();
        }
    }
    // bias for the 8 n columns
    float bias[8];
#pragma unroll
    for (int j = 0; j < 8; ++j) {
        int n = n0 + tx * 8 + j;
        bias[j] = (n < 1024) ? bf[n] : bb[n - 1024];
    }
#pragma unroll
    for (int r = 0; r < 8; ++r) {
        int m = m0 + ty * 8 + r;
        int mp = r >> 1, hi = r & 1;
        float v[8];
#pragma unroll
        for (int j = 0; j < 8; ++j) {
            float2 p = unpack2(acc[mp][j]);
            v[j] = (hi ? p.y : p.x) + bias[j];
        }
        float* cp = g_xproj + (size_t)m * 2048 + n0 + tx * 8;
        *(float4*)cp       = make_float4(v[0], v[1], v[2], v[3]);
        *(float4*)(cp + 4) = make_float4(v[4], v[5], v[6], v[7]);
    }
}

// ---------------- persistent BiLSTM recurrence ----------------
__device__ __forceinline__ void grp_barrier(int grp, unsigned* ls) {
    __syncthreads();
    if (threadIdx.x == 0) {
        *ls ^= 1u;
        __threadfence();
        unsigned old = atomicAdd(&g_cnt[grp * 32], 1u);
        if (old == GRP_SZ - 1) {
            g_cnt[grp * 32] = 0u;
            __threadfence();
            atomicExch(&g_sense[grp * 32], *ls);
        } else {
            while (*(volatile unsigned*)&g_sense[grp * 32] != *ls) { }
            __threadfence();
        }
    }
    __syncthreads();
}

__device__ __forceinline__ float sigf(float x) { return 1.f / (1.f + expf(-x)); }

// 128 blocks: dir(2) x unit-chunk(16, 16 units each) x batch-chunk(4, 16 rows each)
__global__ void __launch_bounds__(256, 1) k_lstm(const float* __restrict__ Whh_f,
                                                 const float* __restrict__ Whh_b) {
    extern __shared__ float sm[];
    float4* W4 = (float4*)sm;                 // [kc(64)][lu(16)][g(4)] = 64KB
    float4* h4 = (float4*)(sm + 16384);       // [kc(64)][lb(16)]       = 16KB

    int bx = blockIdx.x;
    int dir = bx >> 6;
    int rem = bx & 63;
    int uc = rem >> 2;
    int bc = rem & 3;
    int grp = dir * 4 + bc;
    int tid = threadIdx.x;
    int lu = tid >> 4;
    int lb = tid & 15;
    int U = uc * 16 + lu;
    int B0 = bc * 16;
    int b = B0 + lb;
    const float* Whh = dir ? Whh_b : Whh_f;

    for (int i = tid; i < 64 * 64; i += 256) {
        int r = i >> 6;
        int kc = i & 63;
        int lur = r >> 2, g = r & 3;
        int grow = g * 256 + uc * 16 + lur;
        W4[(kc * 16 + lur) * 4 + g] = *(const float4*)(Whh + (size_t)grow * HH + kc * 4);
    }

    float c_st = 0.f;
    unsigned ls = 0;

    for (int s = 0; s < TT; ++s) {
        int t = dir ? (TT - 1 - s) : s;
        // prefetch gate pre-activations BEFORE the barrier (independent of h)
        const float* xp = g_xproj + ((size_t)(t * 64 + b)) * 2048 + dir * 1024 + U;
        float x_i = xp[0];
        float x_f = xp[256];
        float x_g = xp[512];
        float x_o = xp[768];

        u64t a_i = 0ull, a_f = 0ull, a_g = 0ull, a_o = 0ull;
        if (s > 0) {
            grp_barrier(grp, &ls);
            int tp = dir ? (t + 1) : (t - 1);
            const float* hp = g_hcat + ((size_t)(tp * 64 + B0)) * 512 + dir * 256;
#pragma unroll
            for (int i = 0; i < 4; ++i) {
                int idx = i * 256 + tid;
                int c4 = idx >> 4;
                int lbi = idx & 15;
                h4[c4 * 16 + lbi] = *(const float4*)(hp + lbi * 512 + c4 * 4);
            }
        }
        __syncthreads();
        if (s > 0) {
#pragma unroll 4
            for (int kc = 0; kc < 64; ++kc) {
                ulonglong2 hv = *(const ulonglong2*)&h4[kc * 16 + lb];
                const ulonglong2* wr = (const ulonglong2*)&W4[(kc * 16 + lu) * 4];
                ulonglong2 wi = wr[0], wf = wr[1], wg = wr[2], wo = wr[3];
                ffma2(a_i, hv.x, wi.x); ffma2(a_i, hv.y, wi.y);
                ffma2(a_f, hv.x, wf.x); ffma2(a_f, hv.y, wf.y);
                ffma2(a_g, hv.x, wg.x); ffma2(a_g, hv.y, wg.y);
                ffma2(a_o, hv.x, wo.x); ffma2(a_o, hv.y, wo.y);
            }
        }
        float2 vi = unpack2(a_i), vf = unpack2(a_f), vg = unpack2(a_g), vo = unpack2(a_o);
        float pi = vi.x + vi.y + x_i;
        float pf = vf.x + vf.y + x_f;
        float pg = vg.x + vg.y + x_g;
        float po = vo.x + vo.y + x_o;
        c_st = sigf(pf) * c_st + sigf(pi) * tanhf(pg);
        float h = sigf(po) * tanhf(c_st);
        g_hcat[((size_t)(t * 64 + b)) * 512 + dir * 256 + U] = h;
    }
    grp_barrier(grp, &ls); // restore sense parity for next graph replay
}

// ---------------- fc1 + relu + cls -> unary (fused, f32x2 m-paired) ----------------
__global__ void k_fc(const float* __restrict__ W1, const float* __restrict__ b1,
                     const float* __restrict__ Wc, const float* __restrict__ bcls) {
    extern __shared__ float sm[];
    float (*As)[68]  = (float(*)[68])sm;                    // [k][m] 16*68 = 1088 f
    float (*Bs)[132] = (float(*)[132])(sm + 1088);          // [k][n] 16*132 = 2112 f
    float* cls_sh  = sm + 1088 + 2112;                      // 17*128 = 2176 f
    float* clsb_sh = cls_sh + 2176;                         // 32 f
    float* inter   = clsb_sh + 32;                          // 64*132 = 8448 f

    int m0 = blockIdx.x * 64;
    int tid = threadIdx.x;
    int tm = tid >> 4, tn = tid & 15;
    int arow = tid >> 2, aq = (tid & 3) * 4;
    int brow = tid >> 1, bq = tid & 1;

    for (int i = tid; i < 17 * 128; i += 256) cls_sh[i] = Wc[i];
    if (tid < 17) clsb_sh[tid] = bcls[tid];

    u64t acc[2][8];
#pragma unroll
    for (int i = 0; i < 2; ++i)
#pragma unroll
        for (int j = 0; j < 8; ++j) acc[i][j] = 0ull;

    for (int kt = 0; kt < 32; ++kt) {
        int k0 = kt * 16;
        float4 av = *(const float4*)(g_hcat + (size_t)(m0 + arow) * 512 + k0 + aq);
        As[aq + 0][arow] = av.x;
        As[aq + 1][arow] = av.y;
        As[aq + 2][arow] = av.z;
        As[aq + 3][arow] = av.w;
#pragma unroll
        for (int q = 0; q < 2; ++q) {
            float4 bv = *(const float4*)(W1 + (size_t)brow * 512 + k0 + bq * 8 + q * 4);
            Bs[bq * 8 + q * 4 + 0][brow] = bv.x;
            Bs[bq * 8 + q * 4 + 1][brow] = bv.y;
            Bs[bq * 8 + q * 4 + 2][brow] = bv.z;
            Bs[bq * 8 + q * 4 + 3][brow] = bv.w;
        }
        __syncthreads();
#pragma unroll
        for (int k = 0; k < 16; ++k) {
            ulonglong2 aA = *(const ulonglong2*)&As[k][tm * 4];  // 2 m-pairs
            float4 b0 = *(const float4*)&Bs[k][tn * 8];
            float4 b1 = *(const float4*)&Bs[k][tn * 8 + 4];
            u64t bd;
            bd = pack2(b0.x, b0.x); ffma2(acc[0][0], aA.x, bd); ffma2(acc[1][0], aA.y, bd);
            bd = pack2(b0.y, b0.y); ffma2(acc[0][1], aA.x, bd); ffma2(acc[1][1], aA.y, bd);
            bd = pack2(b0.z, b0.z); ffma2(acc[0][2], aA.x, bd); ffma2(acc[1][2], aA.y, bd);
            bd = pack2(b0.w, b0.w); ffma2(acc[0][3], aA.x, bd); ffma2(acc[1][3], aA.y, bd);
            bd = pack2(b1.x, b1.x); ffma2(acc[0][4], aA.x, bd); ffma2(acc[1][4], aA.y, bd);
            bd = pack2(b1.y, b1.y); ffma2(acc[0][5], aA.x, bd); ffma2(acc[1][5], aA.y, bd);
            bd = pack2(b1.z, b1.z); ffma2(acc[0][6], aA.x, bd); ffma2(acc[1][6], aA.y, bd);
            bd = pack2(b1.w, b1.w); ffma2(acc[0][7], aA.x, bd); ffma2(acc[1][7], aA.y, bd);
        }
        __syncthreads();
    }
    // bias + relu -> inter smem
#pragma unroll
    for (int r = 0; r < 4; ++r) {
        int ml = tm * 4 + r;
        int mp = r >> 1, hi = r & 1;
#pragma unroll
        for (int j = 0; j < 8; ++j) {
            float2 p = unpack2(acc[mp][j]);
            int n = tn * 8 + j;
            float v = (hi ? p.y : p.x) + b1[n];
            inter[ml * 132 + n] = v > 0.f ? v : 0.f;
        }
    }
    __syncthreads();
    // second GEMM: 64 x 17 (plus LOW_POT pad to 19), f32x2 over k
    for (int o = tid; o < 64 * TL; o += 256) {
        int ml = o / TL, l = o - ml * TL;
        int m = m0 + ml;
        int t = m >> 6, bat = m & 63;
        float v;
        if (l < NUM_LABELS) {
            u64t s2 = 0ull;
            const ulonglong2* ip = (const ulonglong2*)(inter + ml * 132);
            const ulonglong2* cp = (const ulonglong2*)(cls_sh + l * 128);
#pragma unroll 8
            for (int k4 = 0; k4 < 32; ++k4) {
                ulonglong2 a = ip[k4], c = cp[k4];
                ffma2(s2, a.x, c.x);
                ffma2(s2, a.y, c.y);
            }
            float2 p = unpack2(s2);
            v = clsb_sh[l] + p.x + p.y;
        } else {
            v = LOW_POT;
        }
        g_unary[((size_t)bat * TT + t) * TL + l] = v;
    }
}

// ---------------- Viterbi: one warp per batch element (tree-max argmax) ----------------
__global__ void k_viterbi(const float* __restrict__ trans, float* __restrict__ out,
                          int score_off, int labels_off) {
    __shared__ unsigned char bp[TT * TL];
    int b = blockIdx.x;
    int l = threadIdx.x;

    // transition row tr[l][p] in registers (kills per-step shared/global loads)
    float trrow[TL];
#pragma unroll
    for (int p = 0; p < TL; ++p)
        trrow[p] = (l < TL) ? trans[l * TL + p] : 0.f;
    float tr_end = (l < TL) ? trans[END_IDX * TL + l] : 0.f;

    float score = (l == START_IDX) ? 0.f : LOW_POT;
    const float* ub = g_unary + (size_t)b * TT * TL;

    float u_next = (l < TL) ? ub[l] : LOW_POT;   // prefetch u(0)
    for (int t = 0; t < TT; ++t) {
        float u = u_next;
        int tn = (t + 1 < TT) ? (t + 1) : t;
        u_next = (l < TL) ? ub[tn * TL + l] : LOW_POT;   // prefetch u(t+1), off critical path

        float cand[TL];
#pragma unroll
        for (int p = 0; p < TL; ++p)
            cand[p] = __shfl_sync(0xffffffffu, score, p) + trrow[p];

        // exact tree max (fmaxf over finite floats is exactly associative)
        float a0 = fmaxf(cand[0],  cand[1]);
        float a1 = fmaxf(cand[2],  cand[3]);
        float a2 = fmaxf(cand[4],  cand[5]);
        float a3 = fmaxf(cand[6],  cand[7]);
        float a4 = fmaxf(cand[8],  cand[9]);
        float a5 = fmaxf(cand[10], cand[11]);
        float a6 = fmaxf(cand[12], cand[13]);
        float a7 = fmaxf(cand[14], cand[15]);
        float a8 = fmaxf(cand[16], cand[17]);
        float b0 = fmaxf(a0, a1);
        float b1 = fmaxf(a2, a3);
        float b2 = fmaxf(a4, a5);
        float b3 = fmaxf(a6, a7);
        float b4 = fmaxf(a8, cand[18]);
        float c0 = fmaxf(b0, b1);
        float c1 = fmaxf(b2, b3);
        float d0 = fmaxf(c0, c1);
        float m  = fmaxf(d0, b4);

        score = m + u;   // critical path ends here; mask/ffs/store overlap next step

        // first index equal to max == jnp.argmax tie-break (independent cmps, ILP)
        unsigned mask = 0u;
#pragma unroll
        for (int p = 0; p < TL; ++p)
            mask |= (cand[p] == m) ? (1u << p) : 0u;
        int bi = __ffs(mask) - 1;

        if (l < TL) bp[t * TL + l] = (unsigned char)bi;
    }
    __syncwarp();

    float fin = (l < TL) ? (score + tr_end) : -3.4e38f;
    int idx = (l < TL) ? l : 31;
#pragma unroll
    for (int off = 16; off; off >>= 1) {
        float ov = __shfl_down_sync(0xffffffffu, fin, off);
        int   oi = __shfl_down_sync(0xffffffffu, idx, off);
        if (ov > fin || (ov == fin && oi < idx)) { fin = ov; idx = oi; }
    }
    if (l == 0) {
        if (score_off >= 0) out[score_off + b] = fin;
        if (labels_off >= 0) {
            int lab = idx;
            float* lo = out + labels_off + (size_t)b * TT;
            lo[TT - 1] = (float)lab;
            for (int t = TT - 1; t >= 1; --t) {
                lab = bp[t * TL + lab];
                lo[t - 1] = (float)lab;
            }
        }
    }
}

// ---------------- launch ----------------
extern "C" void kernel_launch(void* const* d_in, const int* in_sizes, int n_in,
                              void* d_out, int out_size) {
    const int*   x        = (const int*)d_in[0];
    const float* emb_tab  = (const float*)d_in[1];
    const float* W_ih_f   = (const float*)d_in[2];
    const float* W_hh_f   = (const float*)d_in[3];
    const float* b_f      = (const float*)d_in[4];
    const float* W_ih_b   = (const float*)d_in[5];
    const float* W_hh_b   = (const float*)d_in[6];
    const float* b_b      = (const float*)d_in[7];
    const float* fc1_W    = (const float*)d_in[8];
    const float* fc1_b    = (const float*)d_in[9];
    const float* cls_W    = (const float*)d_in[10];
    const float* cls_b    = (const float*)d_in[11];
    const float* trans    = (const float*)d_in[12];
    float* out = (float*)d_out;

    cudaFuncSetAttribute(k_lstm, cudaFuncAttributeMaxDynamicSharedMemorySize, 81920);
    cudaFuncSetAttribute(k_fc,   cudaFuncAttributeMaxDynamicSharedMemorySize, 57344);

    dim3 g1(2048 / 128, MTOT / 128);
    k_gemm_xproj<<<g1, 256>>>(x, emb_tab, W_ih_f, W_ih_b, b_f, b_b);

    k_lstm<<<NB_LSTM, 256, 81920>>>(W_hh_f, W_hh_b);

    k_fc<<<MTOT / 64, 256, 57344>>>(fc1_W, fc1_b, cls_W, cls_b);

    int score_off, labels_off;
    if (out_size >= BB + BB * TT) { score_off = 0; labels_off = BB; }
    else if (out_size == BB * TT) { score_off = -1; labels_off = 0; }
    else                          { score_off = 0; labels_off = -1; }
    k_viterbi<<<BB, 32>>>(trans, out, score_off, labels_off);
}

// round 14
// speedup vs baseline: 1.2113x; 1.0391x over previous
#include <cuda_runtime.h>
#include <cuda_bf16.h>
#include <math.h>

// ---------------- problem constants ----------------
#define BB 64
#define TT 256
#define EE 300
#define HH 256
#define INTER 128
#define NUM_LABELS 17
#define TL 19           // TOTAL_LABELS
#define START_IDX 17
#define END_IDX 18
#define LOW_POT -10000.0f

#define MTOT (BB*TT)            // 16384, m = t*64 + b
#define NB_LSTM 128             // persistent blocks
#define GRP_SZ 16               // blocks per barrier group (dir x batch-chunk)

typedef unsigned long long u64t;

// packed fp32x2 FMA (sm_100+): d = a*b + d elementwise, exact IEEE per lane
__device__ __forceinline__ void ffma2(u64t& d, u64t a, u64t b) {
    asm("fma.rn.f32x2 %0, %1, %2, %0;" : "+l"(d) : "l"(a), "l"(b));
}
__device__ __forceinline__ u64t pack2(float lo, float hi) {
    u64t r; asm("mov.b64 %0, {%1,%2};" : "=l"(r) : "f"(lo), "f"(hi)); return r;
}
__device__ __forceinline__ float2 unpack2(u64t v) {
    float2 r; asm("mov.b64 {%0,%1}, %2;" : "=f"(r.x), "=f"(r.y) : "l"(v)); return r;
}

// scoped atomics for the group barrier (replace full MEMBAR.GPU threadfences)
__device__ __forceinline__ unsigned atom_add_acqrel(unsigned* p) {
    unsigned old;
    asm volatile("atom.acq_rel.gpu.add.u32 %0, [%1], 1;" : "=r"(old) : "l"(p) : "memory");
    return old;
}
__device__ __forceinline__ void atom_exch_release(unsigned* p, unsigned v) {
    unsigned d;
    asm volatile("atom.release.gpu.exch.b32 %0, [%1], %2;" : "=r"(d) : "l"(p), "r"(v) : "memory");
}
__device__ __forceinline__ unsigned ld_acquire(const unsigned* p) {
    unsigned v;
    asm volatile("ld.acquire.gpu.u32 %0, [%1];" : "=r"(v) : "l"(p) : "memory");
    return v;
}
__device__ __forceinline__ void st_relaxed(unsigned* p, unsigned v) {
    asm volatile("st.relaxed.gpu.u32 [%0], %1;" :: "l"(p), "r"(v) : "memory");
}

// ---------------- scratch (device globals; allocation-free rule) ----------------
__device__ float g_xproj[(size_t)MTOT * 2048];// [t][b][dir*1024 + g*256 + u]
__device__ float g_hcat[(size_t)MTOT * 512];  // [t][b][dir*256 + u]
__device__ float g_unary[BB * TT * TL];       // [b][t][l]
__device__ unsigned g_cnt[8 * 32];            // per-group barrier counters (padded)
__device__ unsigned g_sense[8 * 32];

// ---------------- x_proj GEMM (fused embedding gather, double-buffered) ----------------
__global__ void __launch_bounds__(256) k_gemm_xproj(
        const int* __restrict__ x, const float* __restrict__ emb,
        const float* __restrict__ Wf, const float* __restrict__ Wb,
        const float* __restrict__ bf, const float* __restrict__ bb) {
    __shared__ float As[2][16][132];   // [buf][k][m] transposed
    __shared__ float Bs[2][16][132];   // [buf][k][n] transposed
    int tid = threadIdx.x;
    int n0 = blockIdx.x * 128;
    int m0 = blockIdx.y * 128;
    int tx = tid & 15, ty = tid >> 4;
    int lrow = tid >> 2;          // 0..63
    int kq = (tid & 3) * 4;       // 0,4,8,12

    int tok[2]; const float* wsrc[2];
#pragma unroll
    for (int it = 0; it < 2; ++it) {
        int m = m0 + lrow + it * 64;
        tok[it] = x[(m & 63) * TT + (m >> 6)];
        int ng = n0 + lrow + it * 64;
        wsrc[it] = (ng < 1024) ? (Wf + (size_t)ng * EE) : (Wb + (size_t)(ng - 1024) * EE);
    }

    u64t acc[4][8];
#pragma unroll
    for (int i = 0; i < 4; ++i)
#pragma unroll
        for (int j = 0; j < 8; ++j) acc[i][j] = 0ull;

    float4 avr[2], bvr[2];
#pragma unroll
    for (int it = 0; it < 2; ++it) {
        avr[it] = make_float4(0.f, 0.f, 0.f, 0.f);
        bvr[it] = make_float4(0.f, 0.f, 0.f, 0.f);
        if (kq < EE) {
            avr[it] = *(const float4*)(emb + (size_t)tok[it] * EE + kq);
            bvr[it] = *(const float4*)(wsrc[it] + kq);
        }
    }
#pragma unroll
    for (int it = 0; it < 2; ++it) {
        int r = lrow + it * 64;
        As[0][kq + 0][r] = avr[it].x; As[0][kq + 1][r] = avr[it].y;
        As[0][kq + 2][r] = avr[it].z; As[0][kq + 3][r] = avr[it].w;
        Bs[0][kq + 0][r] = bvr[it].x; Bs[0][kq + 1][r] = bvr[it].y;
        Bs[0][kq + 2][r] = bvr[it].z; Bs[0][kq + 3][r] = bvr[it].w;
    }
    __syncthreads();

    for (int kt = 0; kt < 19; ++kt) {
        int cur = kt & 1;
        if (kt + 1 < 19) {
            int kb = (kt + 1) * 16 + kq;
#pragma unroll
            for (int it = 0; it < 2; ++it) {
                avr[it] = make_float4(0.f, 0.f, 0.f, 0.f);
                bvr[it] = make_float4(0.f, 0.f, 0.f, 0.f);
                if (kb < EE) {
                    avr[it] = *(const float4*)(emb + (size_t)tok[it] * EE + kb);
                    bvr[it] = *(const float4*)(wsrc[it] + kb);
                }
            }
        }
#pragma unroll
        for (int k = 0; k < 16; ++k) {
            ulonglong2 aA = *(const ulonglong2*)&As[cur][k][ty * 8];
            ulonglong2 aB = *(const ulonglong2*)&As[cur][k][ty * 8 + 4];
            float4 b0 = *(const float4*)&Bs[cur][k][tx * 8];
            float4 b1 = *(const float4*)&Bs[cur][k][tx * 8 + 4];
            u64t bd;
            bd = pack2(b0.x, b0.x); ffma2(acc[0][0], aA.x, bd); ffma2(acc[1][0], aA.y, bd); ffma2(acc[2][0], aB.x, bd); ffma2(acc[3][0], aB.y, bd);
            bd = pack2(b0.y, b0.y); ffma2(acc[0][1], aA.x, bd); ffma2(acc[1][1], aA.y, bd); ffma2(acc[2][1], aB.x, bd); ffma2(acc[3][1], aB.y, bd);
            bd = pack2(b0.z, b0.z); ffma2(acc[0][2], aA.x, bd); ffma2(acc[1][2], aA.y, bd); ffma2(acc[2][2], aB.x, bd); ffma2(acc[3][2], aB.y, bd);
            bd = pack2(b0.w, b0.w); ffma2(acc[0][3], aA.x, bd); ffma2(acc[1][3], aA.y, bd); ffma2(acc[2][3], aB.x, bd); ffma2(acc[3][3], aB.y, bd);
            bd = pack2(b1.x, b1.x); ffma2(acc[0][4], aA.x, bd); ffma2(acc[1][4], aA.y, bd); ffma2(acc[2][4], aB.x, bd); ffma2(acc[3][4], aB.y, bd);
            bd = pack2(b1.y, b1.y); ffma2(acc[0][5], aA.x, bd); ffma2(acc[1][5], aA.y, bd); ffma2(acc[2][5], aB.x, bd); ffma2(acc[3][5], aB.y, bd);
            bd = pack2(b1.z, b1.z); ffma2(acc[0][6], aA.x, bd); ffma2(acc[1][6], aA.y, bd); ffma2(acc[2][6], aB.x, bd); ffma2(acc[3][6], aB.y, bd);
            bd = pack2(b1.w, b1.w); ffma2(acc[0][7], aA.x, bd); ffma2(acc[1][7], aA.y, bd); ffma2(acc[2][7], aB.x, bd); ffma2(acc[3][7], aB.y, bd);
        }
        if (kt + 1 < 19) {
            int nxt = cur ^ 1;
#pragma unroll
            for (int it = 0; it < 2; ++it) {
                int r = lrow + it * 64;
                As[nxt][kq + 0][r] = avr[it].x; As[nxt][kq + 1][r] = avr[it].y;
                As[nxt][kq + 2][r] = avr[it].z; As[nxt][kq + 3][r] = avr[it].w;
                Bs[nxt][kq + 0][r] = bvr[it].x; Bs[nxt][kq + 1][r] = bvr[it].y;
                Bs[nxt][kq + 2][r] = bvr[it].z; Bs[nxt][kq + 3][r] = bvr[it].w;
            }
            __syncthreads();
        }
    }
    float bias[8];
#pragma unroll
    for (int j = 0; j < 8; ++j) {
        int n = n0 + tx * 8 + j;
        bias[j] = (n < 1024) ? bf[n] : bb[n - 1024];
    }
#pragma unroll
    for (int r = 0; r < 8; ++r) {
        int m = m0 + ty * 8 + r;
        int mp = r >> 1, hi = r & 1;
        float v[8];
#pragma unroll
        for (int j = 0; j < 8; ++j) {
            float2 p = unpack2(acc[mp][j]);
            v[j] = (hi ? p.y : p.x) + bias[j];
        }
        float* cp = g_xproj + (size_t)m * 2048 + n0 + tx * 8;
        *(float4*)cp       = make_float4(v[0], v[1], v[2], v[3]);
        *(float4*)(cp + 4) = make_float4(v[4], v[5], v[6], v[7]);
    }
}

// ---------------- persistent BiLSTM recurrence ----------------
__device__ __forceinline__ void grp_barrier(int grp, unsigned* ls) {
    __syncthreads();
    if (threadIdx.x == 0) {
        *ls ^= 1u;
        unsigned old = atom_add_acqrel(&g_cnt[grp * 32]);
        if (old == GRP_SZ - 1) {
            st_relaxed(&g_cnt[grp * 32], 0u);
            atom_exch_release(&g_sense[grp * 32], *ls);
        } else {
            while (ld_acquire(&g_sense[grp * 32]) != *ls) { }
        }
    }
    __syncthreads();
}

__device__ __forceinline__ float sigf(float x) { return 1.f / (1.f + expf(-x)); }

// 128 blocks: dir(2) x unit-chunk(16, 16 units each) x batch-chunk(4, 16 rows each)
// smem: W 64KB | h 16KB | gate tile 4x16x17 floats (coalesced staging)
__global__ void __launch_bounds__(256, 1) k_lstm(const float* __restrict__ Whh_f,
                                                 const float* __restrict__ Whh_b) {
    extern __shared__ float sm[];
    float4* W4 = (float4*)sm;                 // [kc(64)][lu(16)][g(4)] = 64KB
    float4* h4 = (float4*)(sm + 16384);       // [kc(64)][lb(16)]       = 16KB
    float* xg  = sm + 16384 + 4096;           // [g(4)][bb(16)][u'(17 padded)] = 4.25KB

    int bx = blockIdx.x;
    int dir = bx >> 6;
    int rem = bx & 63;
    int uc = rem >> 2;
    int bc = rem & 3;
    int grp = dir * 4 + bc;
    int tid = threadIdx.x;
    int lu = tid >> 4;
    int lb = tid & 15;
    int U = uc * 16 + lu;
    int B0 = bc * 16;
    int b = B0 + lb;
    const float* Whh = dir ? Whh_b : Whh_f;

    // producer mapping for gate staging: 64 chunks (bb,g) x 4 threads x float4
    int chunk = tid >> 2;            // 0..63
    int bb = chunk >> 2;             // 0..15
    int gg = chunk & 3;              // 0..3
    int tq = (tid & 3) * 4;          // 0,4,8,12

    for (int i = tid; i < 64 * 64; i += 256) {
        int r = i >> 6;
        int kc = i & 63;
        int lur = r >> 2, g = r & 3;
        int grow = g * 256 + uc * 16 + lur;
        W4[(kc * 16 + lur) * 4 + g] = *(const float4*)(Whh + (size_t)grow * HH + kc * 4);
    }

    float c_st = 0.f;
    unsigned ls = 0;

    for (int s = 0; s < TT; ++s) {
        int t = dir ? (TT - 1 - s) : s;
        // coalesced gate fetch for this step (64B per 4-thread group), issued
        // BEFORE the barrier so L2 latency hides behind the barrier wait
        const float* gsrc = g_xproj + (size_t)(t * 64 + B0 + bb) * 2048
                            + dir * 1024 + gg * 256 + uc * 16 + tq;
        float4 gv = *(const float4*)gsrc;

        if (s > 0) {
            grp_barrier(grp, &ls);
            int tp = dir ? (t + 1) : (t - 1);
            const float* hp = g_hcat + ((size_t)(tp * 64 + B0)) * 512 + dir * 256;
#pragma unroll
            for (int i = 0; i < 4; ++i) {
                int idx = i * 256 + tid;
                int c4 = idx >> 4;
                int lbi = idx & 15;
                h4[c4 * 16 + lbi] = *(const float4*)(hp + lbi * 512 + c4 * 4);
            }
        }
        // stage gates into smem (prev step's readers retired by barrier sync)
        {
            int base = (gg * 16 + bb) * 17 + tq;
            xg[base + 0] = gv.x; xg[base + 1] = gv.y;
            xg[base + 2] = gv.z; xg[base + 3] = gv.w;
        }
        __syncthreads();

        // consumer gate reads (in flight during the compute loop)
        float x_i = xg[(0 * 16 + lb) * 17 + lu];
        float x_f = xg[(1 * 16 + lb) * 17 + lu];
        float x_g = xg[(2 * 16 + lb) * 17 + lu];
        float x_o = xg[(3 * 16 + lb) * 17 + lu];

        u64t a_i = 0ull, a_f = 0ull, a_g = 0ull, a_o = 0ull;
        if (s > 0) {
#pragma unroll 4
            for (int kc = 0; kc < 64; ++kc) {
                ulonglong2 hv = *(const ulonglong2*)&h4[kc * 16 + lb];
                const ulonglong2* wr = (const ulonglong2*)&W4[(kc * 16 + lu) * 4];
                ulonglong2 wi = wr[0], wf = wr[1], wg = wr[2], wo = wr[3];
                ffma2(a_i, hv.x, wi.x); ffma2(a_i, hv.y, wi.y);
                ffma2(a_f, hv.x, wf.x); ffma2(a_f, hv.y, wf.y);
                ffma2(a_g, hv.x, wg.x); ffma2(a_g, hv.y, wg.y);
                ffma2(a_o, hv.x, wo.x); ffma2(a_o, hv.y, wo.y);
            }
        }
        float2 vi = unpack2(a_i), vf = unpack2(a_f), vg = unpack2(a_g), vo = unpack2(a_o);
        float pi = vi.x + vi.y + x_i;
        float pf = vf.x + vf.y + x_f;
        float pg = vg.x + vg.y + x_g;
        float po = vo.x + vo.y + x_o;
        c_st = sigf(pf) * c_st + sigf(pi) * tanhf(pg);
        float h = sigf(po) * tanhf(c_st);
        g_hcat[((size_t)(t * 64 + b)) * 512 + dir * 256 + U] = h;
    }
    grp_barrier(grp, &ls); // restore sense parity for next graph replay
}

// ---------------- fc1 + relu + cls -> unary (fused, f32x2 m-paired) ----------------
__global__ void k_fc(const float* __restrict__ W1, const float* __restrict__ b1,
                     const float* __restrict__ Wc, const float* __restrict__ bcls) {
    extern __shared__ float sm[];
    float (*As)[68]  = (float(*)[68])sm;                    // [k][m] 16*68 = 1088 f
    float (*Bs)[132] = (float(*)[132])(sm + 1088);          // [k][n] 16*132 = 2112 f
    float* cls_sh  = sm + 1088 + 2112;                      // 17*128 = 2176 f
    float* clsb_sh = cls_sh + 2176;                         // 32 f
    float* inter   = clsb_sh + 32;                          // 64*132 = 8448 f

    int m0 = blockIdx.x * 64;
    int tid = threadIdx.x;
    int tm = tid >> 4, tn = tid & 15;
    int arow = tid >> 2, aq = (tid & 3) * 4;
    int brow = tid >> 1, bq = tid & 1;

    for (int i = tid; i < 17 * 128; i += 256) cls_sh[i] = Wc[i];
    if (tid < 17) clsb_sh[tid] = bcls[tid];

    u64t acc[2][8];
#pragma unroll
    for (int i = 0; i < 2; ++i)
#pragma unroll
        for (int j = 0; j < 8; ++j) acc[i][j] = 0ull;

    for (int kt = 0; kt < 32; ++kt) {
        int k0 = kt * 16;
        float4 av = *(const float4*)(g_hcat + (size_t)(m0 + arow) * 512 + k0 + aq);
        As[aq + 0][arow] = av.x;
        As[aq + 1][arow] = av.y;
        As[aq + 2][arow] = av.z;
        As[aq + 3][arow] = av.w;
#pragma unroll
        for (int q = 0; q < 2; ++q) {
            float4 bv = *(const float4*)(W1 + (size_t)brow * 512 + k0 + bq * 8 + q * 4);
            Bs[bq * 8 + q * 4 + 0][brow] = bv.x;
            Bs[bq * 8 + q * 4 + 1][brow] = bv.y;
            Bs[bq * 8 + q * 4 + 2][brow] = bv.z;
            Bs[bq * 8 + q * 4 + 3][brow] = bv.w;
        }
        __syncthreads();
#pragma unroll
        for (int k = 0; k < 16; ++k) {
            ulonglong2 aA = *(const ulonglong2*)&As[k][tm * 4];
            float4 b0 = *(const float4*)&Bs[k][tn * 8];
            float4 b1 = *(const float4*)&Bs[k][tn * 8 + 4];
            u64t bd;
            bd = pack2(b0.x, b0.x); ffma2(acc[0][0], aA.x, bd); ffma2(acc[1][0], aA.y, bd);
            bd = pack2(b0.y, b0.y); ffma2(acc[0][1], aA.x, bd); ffma2(acc[1][1], aA.y, bd);
            bd = pack2(b0.z, b0.z); ffma2(acc[0][2], aA.x, bd); ffma2(acc[1][2], aA.y, bd);
            bd = pack2(b0.w, b0.w); ffma2(acc[0][3], aA.x, bd); ffma2(acc[1][3], aA.y, bd);
            bd = pack2(b1.x, b1.x); ffma2(acc[0][4], aA.x, bd); ffma2(acc[1][4], aA.y, bd);
            bd = pack2(b1.y, b1.y); ffma2(acc[0][5], aA.x, bd); ffma2(acc[1][5], aA.y, bd);
            bd = pack2(b1.z, b1.z); ffma2(acc[0][6], aA.x, bd); ffma2(acc[1][6], aA.y, bd);
            bd = pack2(b1.w, b1.w); ffma2(acc[0][7], aA.x, bd); ffma2(acc[1][7], aA.y, bd);
        }
        __syncthreads();
    }
#pragma unroll
    for (int r = 0; r < 4; ++r) {
        int ml = tm * 4 + r;
        int mp = r >> 1, hi = r & 1;
#pragma unroll
        for (int j = 0; j < 8; ++j) {
            float2 p = unpack2(acc[mp][j]);
            int n = tn * 8 + j;
            float v = (hi ? p.y : p.x) + b1[n];
            inter[ml * 132 + n] = v > 0.f ? v : 0.f;
        }
    }
    __syncthreads();
    for (int o = tid; o < 64 * TL; o += 256) {
        int ml = o / TL, l = o - ml * TL;
        int m = m0 + ml;
        int t = m >> 6, bat = m & 63;
        float v;
        if (l < NUM_LABELS) {
            u64t s2 = 0ull;
            const ulonglong2* ip = (const ulonglong2*)(inter + ml * 132);
            const ulonglong2* cp = (const ulonglong2*)(cls_sh + l * 128);
#pragma unroll 8
            for (int k4 = 0; k4 < 32; ++k4) {
                ulonglong2 a = ip[k4], c = cp[k4];
                ffma2(s2, a.x, c.x);
                ffma2(s2, a.y, c.y);
            }
            float2 p = unpack2(s2);
            v = clsb_sh[l] + p.x + p.y;
        } else {
            v = LOW_POT;
        }
        g_unary[((size_t)bat * TT + t) * TL + l] = v;
    }
}

// ---------------- Viterbi: smem ping-pong score exchange (no shfl storm) ----------------
__global__ void k_viterbi(const float* __restrict__ trans, float* __restrict__ out,
                          int score_off, int labels_off) {
    __shared__ __align__(16) float sc[2][20];
    __shared__ unsigned char bp[TT * TL];
    int b = blockIdx.x;
    int l = threadIdx.x;

    float trrow[TL];
#pragma unroll
    for (int p = 0; p < TL; ++p)
        trrow[p] = (l < TL) ? trans[l * TL + p] : 0.f;
    float tr_end = (l < TL) ? trans[END_IDX * TL + l] : 0.f;

    if (l < 20) {
        sc[0][l] = (l == START_IDX) ? 0.f : LOW_POT;
        sc[1][l] = LOW_POT;
    }
    __syncwarp();

    const float* ub = g_unary + (size_t)b * TT * TL;
    float u_next  = (l < TL) ? ub[l] : LOW_POT;          // u(0)
    float u_next2 = (l < TL) ? ub[TL + l] : LOW_POT;     // u(1)
    float score = LOW_POT;

    for (int t = 0; t < TT; ++t) {
        int cur = t & 1, nxt = cur ^ 1;
        // broadcast reads of score(t-1): 5x LDS.128, conflict-free
        float4 s0 = *(const float4*)&sc[cur][0];
        float4 s1 = *(const float4*)&sc[cur][4];
        float4 s2 = *(const float4*)&sc[cur][8];
        float4 s3 = *(const float4*)&sc[cur][12];
        float4 s4 = *(const float4*)&sc[cur][16];

        float cand[TL];
        cand[0]  = s0.x + trrow[0];  cand[1]  = s0.y + trrow[1];
        cand[2]  = s0.z + trrow[2];  cand[3]  = s0.w + trrow[3];
        cand[4]  = s1.x + trrow[4];  cand[5]  = s1.y + trrow[5];
        cand[6]  = s1.z + trrow[6];  cand[7]  = s1.w + trrow[7];
        cand[8]  = s2.x + trrow[8];  cand[9]  = s2.y + trrow[9];
        cand[10] = s2.z + trrow[10]; cand[11] = s2.w + trrow[11];
        cand[12] = s3.x + trrow[12]; cand[13] = s3.y + trrow[13];
        cand[14] = s3.z + trrow[14]; cand[15] = s3.w + trrow[15];
        cand[16] = s4.x + trrow[16]; cand[17] = s4.y + trrow[17];
        cand[18] = s4.z + trrow[18];

        // exact tree max
        float a0 = fmaxf(cand[0],  cand[1]);
        float a1 = fmaxf(cand[2],  cand[3]);
        float a2 = fmaxf(cand[4],  cand[5]);
        float a3 = fmaxf(cand[6],  cand[7]);
        float a4 = fmaxf(cand[8],  cand[9]);
        float a5 = fmaxf(cand[10], cand[11]);
        float a6 = fmaxf(cand[12], cand[13]);
        float a7 = fmaxf(cand[14], cand[15]);
        float a8 = fmaxf(cand[16], cand[17]);
        float b0 = fmaxf(a0, a1);
        float b1 = fmaxf(a2, a3);
        float b2 = fmaxf(a4, a5);
        float b3 = fmaxf(a6, a7);
        float b4 = fmaxf(a8, cand[18]);
        float c0 = fmaxf(b0, b1);
        float c1 = fmaxf(b2, b3);
        float d0 = fmaxf(c0, c1);
        float m  = fmaxf(d0, b4);

        float u = u_next;
        u_next = u_next2;
        int tp = (t + 2 < TT) ? (t + 2) : (TT - 1);
        u_next2 = (l < TL) ? ub[tp * TL + l] : LOW_POT;  // depth-2 prefetch

        score = m + u;

        // first index equal to max == jnp.argmax tie-break
        unsigned mask = 0u;
#pragma unroll
        for (int p = 0; p < TL; ++p)
            mask |= (cand[p] == m) ? (1u << p) : 0u;
        int bi = __ffs(mask) - 1;

        if (l < TL) {
            bp[t * TL + l] = (unsigned char)bi;
            sc[nxt][l] = score;
        }
        __syncwarp();
    }

    float fin = (l < TL) ? (score + tr_end) : -3.4e38f;
    int idx = (l < TL) ? l : 31;
#pragma unroll
    for (int off = 16; off; off >>= 1) {
        float ov = __shfl_down_sync(0xffffffffu, fin, off);
        int   oi = __shfl_down_sync(0xffffffffu, idx, off);
        if (ov > fin || (ov == fin && oi < idx)) { fin = ov; idx = oi; }
    }
    if (l == 0) {
        if (score_off >= 0) out[score_off + b] = fin;
        if (labels_off >= 0) {
            int lab = idx;
            float* lo = out + labels_off + (size_t)b * TT;
            lo[TT - 1] = (float)lab;
            for (int t = TT - 1; t >= 1; --t) {
                lab = bp[t * TL + lab];
                lo[t - 1] = (float)lab;
            }
        }
    }
}

// ---------------- launch ----------------
extern "C" void kernel_launch(void* const* d_in, const int* in_sizes, int n_in,
                              void* d_out, int out_size) {
    const int*   x        = (const int*)d_in[0];
    const float* emb_tab  = (const float*)d_in[1];
    const float* W_ih_f   = (const float*)d_in[2];
    const float* W_hh_f   = (const float*)d_in[3];
    const float* b_f      = (const float*)d_in[4];
    const float* W_ih_b   = (const float*)d_in[5];
    const float* W_hh_b   = (const float*)d_in[6];
    const float* b_b      = (const float*)d_in[7];
    const float* fc1_W    = (const float*)d_in[8];
    const float* fc1_b    = (const float*)d_in[9];
    const float* cls_W    = (const float*)d_in[10];
    const float* cls_b    = (const float*)d_in[11];
    const float* trans    = (const float*)d_in[12];
    float* out = (float*)d_out;

    cudaFuncSetAttribute(k_lstm, cudaFuncAttributeMaxDynamicSharedMemorySize, 86272);
    cudaFuncSetAttribute(k_fc,   cudaFuncAttributeMaxDynamicSharedMemorySize, 57344);

    dim3 g1(2048 / 128, MTOT / 128);
    k_gemm_xproj<<<g1, 256>>>(x, emb_tab, W_ih_f, W_ih_b, b_f, b_b);

    k_lstm<<<NB_LSTM, 256, 86272>>>(W_hh_f, W_hh_b);

    k_fc<<<MTOT / 64, 256, 57344>>>(fc1_W, fc1_b, cls_W, cls_b);

    int score_off, labels_off;
    if (out_size >= BB + BB * TT) { score_off = 0; labels_off = BB; }
    else if (out_size == BB * TT) { score_off = -1; labels_off = 0; }
    else                          { score_off = 0; labels_off = -1; }
    k_viterbi<<<BB, 32>>>(trans, out, score_off, labels_off);
}

// round 15
// speedup vs baseline: 1.2144x; 1.0026x over previous
#include <cuda_runtime.h>
#include <cuda_bf16.h>
#include <math.h>

// ---------------- problem constants ----------------
#define BB 64
#define TT 256
#define EE 300
#define HH 256
#define INTER 128
#define NUM_LABELS 17
#define TL 19           // TOTAL_LABELS
#define START_IDX 17
#define END_IDX 18
#define LOW_POT -10000.0f

#define MTOT (BB*TT)            // 16384, m = t*64 + b
#define NB_LSTM 128             // persistent blocks
#define GRP_SZ 16               // blocks per barrier group (dir x batch-chunk)

typedef unsigned long long u64t;

// packed fp32x2 FMA (sm_100+): d = a*b + d elementwise, exact IEEE per lane
__device__ __forceinline__ void ffma2(u64t& d, u64t a, u64t b) {
    asm("fma.rn.f32x2 %0, %1, %2, %0;" : "+l"(d) : "l"(a), "l"(b));
}
__device__ __forceinline__ u64t pack2(float lo, float hi) {
    u64t r; asm("mov.b64 %0, {%1,%2};" : "=l"(r) : "f"(lo), "f"(hi)); return r;
}
__device__ __forceinline__ float2 unpack2(u64t v) {
    float2 r; asm("mov.b64 {%0,%1}, %2;" : "=f"(r.x), "=f"(r.y) : "l"(v)); return r;
}

// scoped atomics for the group barrier (no full MEMBAR.GPU)
__device__ __forceinline__ unsigned atom_add_acqrel(unsigned* p) {
    unsigned old;
    asm volatile("atom.acq_rel.gpu.add.u32 %0, [%1], 1;" : "=r"(old) : "l"(p) : "memory");
    return old;
}
__device__ __forceinline__ void atom_exch_release(unsigned* p, unsigned v) {
    unsigned d;
    asm volatile("atom.release.gpu.exch.b32 %0, [%1], %2;" : "=r"(d) : "l"(p), "r"(v) : "memory");
}
__device__ __forceinline__ unsigned ld_acquire(const unsigned* p) {
    unsigned v;
    asm volatile("ld.acquire.gpu.u32 %0, [%1];" : "=r"(v) : "l"(p) : "memory");
    return v;
}
__device__ __forceinline__ void st_relaxed(unsigned* p, unsigned v) {
    asm volatile("st.relaxed.gpu.u32 [%0], %1;" :: "l"(p), "r"(v) : "memory");
}

// ---------------- scratch (device globals; allocation-free rule) ----------------
__device__ float g_xproj[(size_t)MTOT * 2048];// [t][b][dir*1024 + g*256 + u]
__device__ float g_hcat[(size_t)MTOT * 512];  // [t][b][dir*256 + u]
__device__ float g_unary[BB * TT * TL];       // [b][t][l]
__device__ unsigned g_cnt[8 * 32];            // per-group barrier counters (padded)
__device__ unsigned g_sense[8 * 32];

// ---------------- ncu probe: shift the -s window onto a big kernel ----------------
__global__ void k_noop() {}

// ---------------- x_proj GEMM (fused embedding gather, double-buffered) ----------------
__global__ void __launch_bounds__(256) k_gemm_xproj(
        const int* __restrict__ x, const float* __restrict__ emb,
        const float* __restrict__ Wf, const float* __restrict__ Wb,
        const float* __restrict__ bf, const float* __restrict__ bb) {
    __shared__ float As[2][16][132];   // [buf][k][m] transposed
    __shared__ float Bs[2][16][132];   // [buf][k][n] transposed
    int tid = threadIdx.x;
    int n0 = blockIdx.x * 128;
    int m0 = blockIdx.y * 128;
    int tx = tid & 15, ty = tid >> 4;
    int lrow = tid >> 2;          // 0..63
    int kq = (tid & 3) * 4;       // 0,4,8,12

    int tok[2]; const float* wsrc[2];
#pragma unroll
    for (int it = 0; it < 2; ++it) {
        int m = m0 + lrow + it * 64;
        tok[it] = x[(m & 63) * TT + (m >> 6)];
        int ng = n0 + lrow + it * 64;
        wsrc[it] = (ng < 1024) ? (Wf + (size_t)ng * EE) : (Wb + (size_t)(ng - 1024) * EE);
    }

    u64t acc[4][8];
#pragma unroll
    for (int i = 0; i < 4; ++i)
#pragma unroll
        for (int j = 0; j < 8; ++j) acc[i][j] = 0ull;

    float4 avr[2], bvr[2];
#pragma unroll
    for (int it = 0; it < 2; ++it) {
        avr[it] = make_float4(0.f, 0.f, 0.f, 0.f);
        bvr[it] = make_float4(0.f, 0.f, 0.f, 0.f);
        if (kq < EE) {
            avr[it] = *(const float4*)(emb + (size_t)tok[it] * EE + kq);
            bvr[it] = *(const float4*)(wsrc[it] + kq);
        }
    }
#pragma unroll
    for (int it = 0; it < 2; ++it) {
        int r = lrow + it * 64;
        As[0][kq + 0][r] = avr[it].x; As[0][kq + 1][r] = avr[it].y;
        As[0][kq + 2][r] = avr[it].z; As[0][kq + 3][r] = avr[it].w;
        Bs[0][kq + 0][r] = bvr[it].x; Bs[0][kq + 1][r] = bvr[it].y;
        Bs[0][kq + 2][r] = bvr[it].z; Bs[0][kq + 3][r] = bvr[it].w;
    }
    __syncthreads();

    for (int kt = 0; kt < 19; ++kt) {
        int cur = kt & 1;
        if (kt + 1 < 19) {
            int kb = (kt + 1) * 16 + kq;
#pragma unroll
            for (int it = 0; it < 2; ++it) {
                avr[it] = make_float4(0.f, 0.f, 0.f, 0.f);
                bvr[it] = make_float4(0.f, 0.f, 0.f, 0.f);
                if (kb < EE) {
                    avr[it] = *(const float4*)(emb + (size_t)tok[it] * EE + kb);
                    bvr[it] = *(const float4*)(wsrc[it] + kb);
                }
            }
        }
#pragma unroll
        for (int k = 0; k < 16; ++k) {
            ulonglong2 aA = *(const ulonglong2*)&As[cur][k][ty * 8];
            ulonglong2 aB = *(const ulonglong2*)&As[cur][k][ty * 8 + 4];
            float4 b0 = *(const float4*)&Bs[cur][k][tx * 8];
            float4 b1 = *(const float4*)&Bs[cur][k][tx * 8 + 4];
            u64t bd;
            bd = pack2(b0.x, b0.x); ffma2(acc[0][0], aA.x, bd); ffma2(acc[1][0], aA.y, bd); ffma2(acc[2][0], aB.x, bd); ffma2(acc[3][0], aB.y, bd);
            bd = pack2(b0.y, b0.y); ffma2(acc[0][1], aA.x, bd); ffma2(acc[1][1], aA.y, bd); ffma2(acc[2][1], aB.x, bd); ffma2(acc[3][1], aB.y, bd);
            bd = pack2(b0.z, b0.z); ffma2(acc[0][2], aA.x, bd); ffma2(acc[1][2], aA.y, bd); ffma2(acc[2][2], aB.x, bd); ffma2(acc[3][2], aB.y, bd);
            bd = pack2(b0.w, b0.w); ffma2(acc[0][3], aA.x, bd); ffma2(acc[1][3], aA.y, bd); ffma2(acc[2][3], aB.x, bd); ffma2(acc[3][3], aB.y, bd);
            bd = pack2(b1.x, b1.x); ffma2(acc[0][4], aA.x, bd); ffma2(acc[1][4], aA.y, bd); ffma2(acc[2][4], aB.x, bd); ffma2(acc[3][4], aB.y, bd);
            bd = pack2(b1.y, b1.y); ffma2(acc[0][5], aA.x, bd); ffma2(acc[1][5], aA.y, bd); ffma2(acc[2][5], aB.x, bd); ffma2(acc[3][5], aB.y, bd);
            bd = pack2(b1.z, b1.z); ffma2(acc[0][6], aA.x, bd); ffma2(acc[1][6], aA.y, bd); ffma2(acc[2][6], aB.x, bd); ffma2(acc[3][6], aB.y, bd);
            bd = pack2(b1.w, b1.w); ffma2(acc[0][7], aA.x, bd); ffma2(acc[1][7], aA.y, bd); ffma2(acc[2][7], aB.x, bd); ffma2(acc[3][7], aB.y, bd);
        }
        if (kt + 1 < 19) {
            int nxt = cur ^ 1;
#pragma unroll
            for (int it = 0; it < 2; ++it) {
                int r = lrow + it * 64;
                As[nxt][kq + 0][r] = avr[it].x; As[nxt][kq + 1][r] = avr[it].y;
                As[nxt][kq + 2][r] = avr[it].z; As[nxt][kq + 3][r] = avr[it].w;
                Bs[nxt][kq + 0][r] = bvr[it].x; Bs[nxt][kq + 1][r] = bvr[it].y;
                Bs[nxt][kq + 2][r] = bvr[it].z; Bs[nxt][kq + 3][r] = bvr[it].w;
            }
            __syncthreads();
        }
    }
    float bias[8];
#pragma unroll
    for (int j = 0; j < 8; ++j) {
        int n = n0 + tx * 8 + j;
        bias[j] = (n < 1024) ? bf[n] : bb[n - 1024];
    }
#pragma unroll
    for (int r = 0; r < 8; ++r) {
        int m = m0 + ty * 8 + r;
        int mp = r >> 1, hi = r & 1;
        float v[8];
#pragma unroll
        for (int j = 0; j < 8; ++j) {
            float2 p = unpack2(acc[mp][j]);
            v[j] = (hi ? p.y : p.x) + bias[j];
        }
        float* cp = g_xproj + (size_t)m * 2048 + n0 + tx * 8;
        *(float4*)cp       = make_float4(v[0], v[1], v[2], v[3]);
        *(float4*)(cp + 4) = make_float4(v[4], v[5], v[6], v[7]);
    }
}

// ---------------- persistent BiLSTM recurrence ----------------
__device__ __forceinline__ void grp_barrier(int grp, unsigned* ls) {
    __syncthreads();
    if (threadIdx.x == 0) {
        *ls ^= 1u;
        unsigned old = atom_add_acqrel(&g_cnt[grp * 32]);
        if (old == GRP_SZ - 1) {
            st_relaxed(&g_cnt[grp * 32], 0u);
            atom_exch_release(&g_sense[grp * 32], *ls);
        } else {
            while (ld_acquire(&g_sense[grp * 32]) != *ls) { }
        }
    }
    __syncthreads();
}

__device__ __forceinline__ float sigf(float x) { return 1.f / (1.f + expf(-x)); }

// 128 blocks: dir(2) x unit-chunk(16, 16 units each) x batch-chunk(4, 16 rows each)
__global__ void __launch_bounds__(256, 1) k_lstm(const float* __restrict__ Whh_f,
                                                 const float* __restrict__ Whh_b) {
    extern __shared__ float sm[];
    float4* W4 = (float4*)sm;                 // [kc(64)][lu(16)][g(4)] = 64KB
    float4* h4 = (float4*)(sm + 16384);       // [kc(64)][lb(16)]       = 16KB
    float* xg  = sm + 16384 + 4096;           // [g(4)][bb(16)][u'(17)] = 4.25KB

    int bx = blockIdx.x;
    int dir = bx >> 6;
    int rem = bx & 63;
    int uc = rem >> 2;
    int bc = rem & 3;
    int grp = dir * 4 + bc;
    int tid = threadIdx.x;
    int lu = tid >> 4;
    int lb = tid & 15;
    int U = uc * 16 + lu;
    int B0 = bc * 16;
    int b = B0 + lb;
    const float* Whh = dir ? Whh_b : Whh_f;

    int chunk = tid >> 2;
    int bb = chunk >> 2;
    int gg = chunk & 3;
    int tq = (tid & 3) * 4;

    for (int i = tid; i < 64 * 64; i += 256) {
        int r = i >> 6;
        int kc = i & 63;
        int lur = r >> 2, g = r & 3;
        int grow = g * 256 + uc * 16 + lur;
        W4[(kc * 16 + lur) * 4 + g] = *(const float4*)(Whh + (size_t)grow * HH + kc * 4);
    }

    float c_st = 0.f;
    unsigned ls = 0;

    for (int s = 0; s < TT; ++s) {
        int t = dir ? (TT - 1 - s) : s;
        const float* gsrc = g_xproj + (size_t)(t * 64 + B0 + bb) * 2048
                            + dir * 1024 + gg * 256 + uc * 16 + tq;
        float4 gv = *(const float4*)gsrc;

        if (s > 0) {
            grp_barrier(grp, &ls);
            int tp = dir ? (t + 1) : (t - 1);
            const float* hp = g_hcat + ((size_t)(tp * 64 + B0)) * 512 + dir * 256;
#pragma unroll
            for (int i = 0; i < 4; ++i) {
                int idx = i * 256 + tid;
                int c4 = idx >> 4;
                int lbi = idx & 15;
                h4[c4 * 16 + lbi] = *(const float4*)(hp + lbi * 512 + c4 * 4);
            }
        }
        {
            int base = (gg * 16 + bb) * 17 + tq;
            xg[base + 0] = gv.x; xg[base + 1] = gv.y;
            xg[base + 2] = gv.z; xg[base + 3] = gv.w;
        }
        __syncthreads();

        float x_i = xg[(0 * 16 + lb) * 17 + lu];
        float x_f = xg[(1 * 16 + lb) * 17 + lu];
        float x_g = xg[(2 * 16 + lb) * 17 + lu];
        float x_o = xg[(3 * 16 + lb) * 17 + lu];

        u64t a_i = 0ull, a_f = 0ull, a_g = 0ull, a_o = 0ull;
        if (s > 0) {
#pragma unroll 4
            for (int kc = 0; kc < 64; ++kc) {
                ulonglong2 hv = *(const ulonglong2*)&h4[kc * 16 + lb];
                const ulonglong2* wr = (const ulonglong2*)&W4[(kc * 16 + lu) * 4];
                ulonglong2 wi = wr[0], wf = wr[1], wg = wr[2], wo = wr[3];
                ffma2(a_i, hv.x, wi.x); ffma2(a_i, hv.y, wi.y);
                ffma2(a_f, hv.x, wf.x); ffma2(a_f, hv.y, wf.y);
                ffma2(a_g, hv.x, wg.x); ffma2(a_g, hv.y, wg.y);
                ffma2(a_o, hv.x, wo.x); ffma2(a_o, hv.y, wo.y);
            }
        }
        float2 vi = unpack2(a_i), vf = unpack2(a_f), vg = unpack2(a_g), vo = unpack2(a_o);
        float pi = vi.x + vi.y + x_i;
        float pf = vf.x + vf.y + x_f;
        float pg = vg.x + vg.y + x_g;
        float po = vo.x + vo.y + x_o;
        c_st = sigf(pf) * c_st + sigf(pi) * tanhf(pg);
        float h = sigf(po) * tanhf(c_st);
        g_hcat[((size_t)(t * 64 + b)) * 512 + dir * 256 + U] = h;
    }
    grp_barrier(grp, &ls); // restore sense parity for next graph replay
}

// ---------------- fc1 + relu + cls -> unary (fused, f32x2 m-paired) ----------------
__global__ void k_fc(const float* __restrict__ W1, const float* __restrict__ b1,
                     const float* __restrict__ Wc, const float* __restrict__ bcls) {
    extern __shared__ float sm[];
    float (*As)[68]  = (float(*)[68])sm;                    // [k][m] 16*68 = 1088 f
    float (*Bs)[132] = (float(*)[132])(sm + 1088);          // [k][n] 16*132 = 2112 f
    float* cls_sh  = sm + 1088 + 2112;                      // 17*128 = 2176 f
    float* clsb_sh = cls_sh + 2176;                         // 32 f
    float* inter   = clsb_sh + 32;                          // 64*132 = 8448 f

    int m0 = blockIdx.x * 64;
    int tid = threadIdx.x;
    int tm = tid >> 4, tn = tid & 15;
    int arow = tid >> 2, aq = (tid & 3) * 4;
    int brow = tid >> 1, bq = tid & 1;

    for (int i = tid; i < 17 * 128; i += 256) cls_sh[i] = Wc[i];
    if (tid < 17) clsb_sh[tid] = bcls[tid];

    u64t acc[2][8];
#pragma unroll
    for (int i = 0; i < 2; ++i)
#pragma unroll
        for (int j = 0; j < 8; ++j) acc[i][j] = 0ull;

    for (int kt = 0; kt < 32; ++kt) {
        int k0 = kt * 16;
        float4 av = *(const float4*)(g_hcat + (size_t)(m0 + arow) * 512 + k0 + aq);
        As[aq + 0][arow] = av.x;
        As[aq + 1][arow] = av.y;
        As[aq + 2][arow] = av.z;
        As[aq + 3][arow] = av.w;
#pragma unroll
        for (int q = 0; q < 2; ++q) {
            float4 bv = *(const float4*)(W1 + (size_t)brow * 512 + k0 + bq * 8 + q * 4);
            Bs[bq * 8 + q * 4 + 0][brow] = bv.x;
            Bs[bq * 8 + q * 4 + 1][brow] = bv.y;
            Bs[bq * 8 + q * 4 + 2][brow] = bv.z;
            Bs[bq * 8 + q * 4 + 3][brow] = bv.w;
        }
        __syncthreads();
#pragma unroll
        for (int k = 0; k < 16; ++k) {
            ulonglong2 aA = *(const ulonglong2*)&As[k][tm * 4];
            float4 b0 = *(const float4*)&Bs[k][tn * 8];
            float4 b1 = *(const float4*)&Bs[k][tn * 8 + 4];
            u64t bd;
            bd = pack2(b0.x, b0.x); ffma2(acc[0][0], aA.x, bd); ffma2(acc[1][0], aA.y, bd);
            bd = pack2(b0.y, b0.y); ffma2(acc[0][1], aA.x, bd); ffma2(acc[1][1], aA.y, bd);
            bd = pack2(b0.z, b0.z); ffma2(acc[0][2], aA.x, bd); ffma2(acc[1][2], aA.y, bd);
            bd = pack2(b0.w, b0.w); ffma2(acc[0][3], aA.x, bd); ffma2(acc[1][3], aA.y, bd);
            bd = pack2(b1.x, b1.x); ffma2(acc[0][4], aA.x, bd); ffma2(acc[1][4], aA.y, bd);
            bd = pack2(b1.y, b1.y); ffma2(acc[0][5], aA.x, bd); ffma2(acc[1][5], aA.y, bd);
            bd = pack2(b1.z, b1.z); ffma2(acc[0][6], aA.x, bd); ffma2(acc[1][6], aA.y, bd);
            bd = pack2(b1.w, b1.w); ffma2(acc[0][7], aA.x, bd); ffma2(acc[1][7], aA.y, bd);
        }
        __syncthreads();
    }
#pragma unroll
    for (int r = 0; r < 4; ++r) {
        int ml = tm * 4 + r;
        int mp = r >> 1, hi = r & 1;
#pragma unroll
        for (int j = 0; j < 8; ++j) {
            float2 p = unpack2(acc[mp][j]);
            int n = tn * 8 + j;
            float v = (hi ? p.y : p.x) + b1[n];
            inter[ml * 132 + n] = v > 0.f ? v : 0.f;
        }
    }
    __syncthreads();
    for (int o = tid; o < 64 * TL; o += 256) {
        int ml = o / TL, l = o - ml * TL;
        int m = m0 + ml;
        int t = m >> 6, bat = m & 63;
        float v;
        if (l < NUM_LABELS) {
            u64t s2 = 0ull;
            const ulonglong2* ip = (const ulonglong2*)(inter + ml * 132);
            const ulonglong2* cp = (const ulonglong2*)(cls_sh + l * 128);
#pragma unroll 8
            for (int k4 = 0; k4 < 32; ++k4) {
                ulonglong2 a = ip[k4], c = cp[k4];
                ffma2(s2, a.x, c.x);
                ffma2(s2, a.y, c.y);
            }
            float2 p = unpack2(s2);
            v = clsb_sh[l] + p.x + p.y;
        } else {
            v = LOW_POT;
        }
        g_unary[((size_t)bat * TT + t) * TL + l] = v;
    }
}

// ---------------- Viterbi: slim serial forward + parallel backpointer phase ----------------
// Forward (warp 0, serial over t): only max+score -> hist[t+1]. ~48 instrs/step.
// BP phase (4 warps, parallel over 255x19): recompute argmax from hist (exact
// same adds + first-max linear scan as the reference semantics).
__global__ void __launch_bounds__(128) k_viterbi(const float* __restrict__ trans,
                                                 float* __restrict__ out,
                                                 int score_off, int labels_off) {
    __shared__ __align__(16) float hist[257][20];   // hist[t] = score before step t
    __shared__ float T_sh[TL * TL];
    __shared__ unsigned char bp[256 * TL];
    __shared__ int s_last;
    int bIdx = blockIdx.x;
    int tid = threadIdx.x;
    int l = tid & 31;
    int wid = tid >> 5;

    for (int i = tid; i < TL * TL; i += 128) T_sh[i] = trans[i];
    if (tid < 20) hist[0][tid] = (tid == START_IDX) ? 0.f : LOW_POT;
    __syncthreads();

    if (wid == 0) {
        float trrow[TL];
#pragma unroll
        for (int p = 0; p < TL; ++p) trrow[p] = (l < TL) ? T_sh[l * TL + p] : 0.f;
        float tr_end = (l < TL) ? T_sh[END_IDX * TL + l] : 0.f;

        const float* ub = g_unary + (size_t)bIdx * TT * TL;
        float u_next  = (l < TL) ? ub[l] : LOW_POT;
        float u_next2 = (l < TL) ? ub[TL + l] : LOW_POT;
        float score = LOW_POT;

        for (int t = 0; t < TT; ++t) {
            float4 s0 = *(const float4*)&hist[t][0];
            float4 s1 = *(const float4*)&hist[t][4];
            float4 s2 = *(const float4*)&hist[t][8];
            float4 s3 = *(const float4*)&hist[t][12];
            float4 s4 = *(const float4*)&hist[t][16];

            float c0  = s0.x + trrow[0],  c1  = s0.y + trrow[1];
            float c2  = s0.z + trrow[2],  c3  = s0.w + trrow[3];
            float c4  = s1.x + trrow[4],  c5  = s1.y + trrow[5];
            float c6  = s1.z + trrow[6],  c7  = s1.w + trrow[7];
            float c8  = s2.x + trrow[8],  c9  = s2.y + trrow[9];
            float c10 = s2.z + trrow[10], c11 = s2.w + trrow[11];
            float c12 = s3.x + trrow[12], c13 = s3.y + trrow[13];
            float c14 = s3.z + trrow[14], c15 = s3.w + trrow[15];
            float c16 = s4.x + trrow[16], c17 = s4.y + trrow[17];
            float c18 = s4.z + trrow[18];

            float a0 = fmaxf(c0, c1),  a1 = fmaxf(c2, c3);
            float a2 = fmaxf(c4, c5),  a3 = fmaxf(c6, c7);
            float a4 = fmaxf(c8, c9),  a5 = fmaxf(c10, c11);
            float a6 = fmaxf(c12, c13), a7 = fmaxf(c14, c15);
            float a8 = fmaxf(c16, c17);
            float b0 = fmaxf(a0, a1), b1 = fmaxf(a2, a3);
            float b2 = fmaxf(a4, a5), b3 = fmaxf(a6, a7);
            float b4 = fmaxf(a8, c18);
            float d0 = fmaxf(b0, b1), d1 = fmaxf(b2, b3);
            float m  = fmaxf(fmaxf(d0, d1), b4);

            float u = u_next;
            u_next = u_next2;
            int tp = (t + 2 < TT) ? (t + 2) : (TT - 1);
            u_next2 = (l < TL) ? ub[tp * TL + l] : LOW_POT;

            score = m + u;
            if (l < TL) hist[t + 1][l] = score;
            __syncwarp();
        }

        // final argmax (first-index tie-break) + path score
        float fin = (l < TL) ? (score + tr_end) : -3.4e38f;
        int idx = (l < TL) ? l : 31;
#pragma unroll
        for (int off = 16; off; off >>= 1) {
            float ov = __shfl_down_sync(0xffffffffu, fin, off);
            int   oi = __shfl_down_sync(0xffffffffu, idx, off);
            if (ov > fin || (ov == fin && oi < idx)) { fin = ov; idx = oi; }
        }
        if (l == 0) {
            s_last = idx;
            if (score_off >= 0) out[score_off + bIdx] = fin;
        }
    }
    __syncthreads();

    // parallel backpointer phase: t = 1..255 (t=0 never consumed by backtrace)
    for (int i = tid; i < 255 * TL; i += 128) {
        int t = 1 + i / TL;
        int ll = i - (i / TL) * TL;
        const float* hp = &hist[t][0];           // score before step t
        const float* tr = &T_sh[ll * TL];
        float best = -3.4e38f; int bi = 0;
#pragma unroll
        for (int p = 0; p < TL; ++p) {
            float v = hp[p] + tr[p];
            if (v > best) { best = v; bi = p; }  // strict > = first max (jnp.argmax)
        }
        bp[t * TL + ll] = (unsigned char)bi;
    }
    __syncthreads();

    if (tid == 0 && labels_off >= 0) {
        int lab = s_last;
        float* lo = out + labels_off + (size_t)bIdx * TT;
        lo[TT - 1] = (float)lab;
        for (int t = TT - 1; t >= 1; --t) {
            lab = bp[t * TL + lab];
            lo[t - 1] = (float)lab;
        }
    }
}

// ---------------- launch ----------------
extern "C" void kernel_launch(void* const* d_in, const int* in_sizes, int n_in,
                              void* d_out, int out_size) {
    const int*   x        = (const int*)d_in[0];
    const float* emb_tab  = (const float*)d_in[1];
    const float* W_ih_f   = (const float*)d_in[2];
    const float* W_hh_f   = (const float*)d_in[3];
    const float* b_f      = (const float*)d_in[4];
    const float* W_ih_b   = (const float*)d_in[5];
    const float* W_hh_b   = (const float*)d_in[6];
    const float* b_b      = (const float*)d_in[7];
    const float* fc1_W    = (const float*)d_in[8];
    const float* fc1_b    = (const float*)d_in[9];
    const float* cls_W    = (const float*)d_in[10];
    const float* cls_b    = (const float*)d_in[11];
    const float* trans    = (const float*)d_in[12];
    float* out = (float*)d_out;

    cudaFuncSetAttribute(k_lstm, cudaFuncAttributeMaxDynamicSharedMemorySize, 86272);
    cudaFuncSetAttribute(k_fc,   cudaFuncAttributeMaxDynamicSharedMemorySize, 57344);

    // ncu probe: shift the -s capture window off k_viterbi onto a big kernel
    k_noop<<<1, 32>>>();
    k_noop<<<1, 32>>>();
    k_noop<<<1, 32>>>();

    dim3 g1(2048 / 128, MTOT / 128);
    k_gemm_xproj<<<g1, 256>>>(x, emb_tab, W_ih_f, W_ih_b, b_f, b_b);

    k_lstm<<<NB_LSTM, 256, 86272>>>(W_hh_f, W_hh_b);

    k_fc<<<MTOT / 64, 256, 57344>>>(fc1_W, fc1_b, cls_W, cls_b);

    int score_off, labels_off;
    if (out_size >= BB + BB * TT) { score_off = 0; labels_off = BB; }
    else if (out_size == BB * TT) { score_off = -1; labels_off = 0; }
    else                          { score_off = 0; labels_off = -1; }
    k_viterbi<<<BB, 128>>>(trans, out, score_off, labels_off);
}

// round 16
// speedup vs baseline: 1.2376x; 1.0191x over previous
#include <cuda_runtime.h>
#include <cuda_bf16.h>
#include <math.h>

// ---------------- problem constants ----------------
#define BB 64
#define TT 256
#define EE 300
#define HH 256
#define INTER 128
#define NUM_LABELS 17
#define TL 19           // TOTAL_LABELS
#define START_IDX 17
#define END_IDX 18
#define LOW_POT -10000.0f

#define MTOT (BB*TT)            // 16384, m = t*64 + b
#define NB_LSTM 128             // persistent blocks
#define GRP_SZ 16               // blocks per barrier group (dir x batch-chunk)

typedef unsigned long long u64t;

// packed fp32x2 FMA (sm_100+): d = a*b + d elementwise, exact IEEE per lane
__device__ __forceinline__ void ffma2(u64t& d, u64t a, u64t b) {
    asm("fma.rn.f32x2 %0, %1, %2, %0;" : "+l"(d) : "l"(a), "l"(b));
}
__device__ __forceinline__ u64t pack2(float lo, float hi) {
    u64t r; asm("mov.b64 %0, {%1,%2};" : "=l"(r) : "f"(lo), "f"(hi)); return r;
}
__device__ __forceinline__ float2 unpack2(u64t v) {
    float2 r; asm("mov.b64 {%0,%1}, %2;" : "=f"(r.x), "=f"(r.y) : "l"(v)); return r;
}

// scoped release/acquire for the distributed barrier
__device__ __forceinline__ void st_release(unsigned* p, unsigned v) {
    asm volatile("st.release.gpu.u32 [%0], %1;" :: "l"(p), "r"(v) : "memory");
}
__device__ __forceinline__ unsigned ld_acquire(const unsigned* p) {
    unsigned v;
    asm volatile("ld.acquire.gpu.u32 %0, [%1];" : "=r"(v) : "l"(p) : "memory");
    return v;
}

// ---------------- scratch (device globals; allocation-free rule) ----------------
__device__ float g_xproj[(size_t)MTOT * 2048];// [t][b][dir*1024 + g*256 + u]
__device__ float g_hcat[(size_t)MTOT * 512];  // [t][b][dir*256 + u]
__device__ float g_unary[BB * TT * TL];       // [b][t][l]
__device__ unsigned g_flag[8 * 16 * 32];      // [grp][member] monotonic step flags (128B padded)

// ---------------- ncu probe: put k_lstm at launch index 3 ----------------
__global__ void k_noop() {}

// ---------------- x_proj GEMM (fused embedding gather, double-buffered) ----------------
__global__ void __launch_bounds__(256) k_gemm_xproj(
        const int* __restrict__ x, const float* __restrict__ emb,
        const float* __restrict__ Wf, const float* __restrict__ Wb,
        const float* __restrict__ bf, const float* __restrict__ bb) {
    __shared__ float As[2][16][132];   // [buf][k][m] transposed
    __shared__ float Bs[2][16][132];   // [buf][k][n] transposed
    int tid = threadIdx.x;
    int n0 = blockIdx.x * 128;
    int m0 = blockIdx.y * 128;
    int tx = tid & 15, ty = tid >> 4;
    int lrow = tid >> 2;          // 0..63
    int kq = (tid & 3) * 4;       // 0,4,8,12

    int tok[2]; const float* wsrc[2];
#pragma unroll
    for (int it = 0; it < 2; ++it) {
        int m = m0 + lrow + it * 64;
        tok[it] = x[(m & 63) * TT + (m >> 6)];
        int ng = n0 + lrow + it * 64;
        wsrc[it] = (ng < 1024) ? (Wf + (size_t)ng * EE) : (Wb + (size_t)(ng - 1024) * EE);
    }

    u64t acc[4][8];
#pragma unroll
    for (int i = 0; i < 4; ++i)
#pragma unroll
        for (int j = 0; j < 8; ++j) acc[i][j] = 0ull;

    float4 avr[2], bvr[2];
#pragma unroll
    for (int it = 0; it < 2; ++it) {
        avr[it] = make_float4(0.f, 0.f, 0.f, 0.f);
        bvr[it] = make_float4(0.f, 0.f, 0.f, 0.f);
        if (kq < EE) {
            avr[it] = *(const float4*)(emb + (size_t)tok[it] * EE + kq);
            bvr[it] = *(const float4*)(wsrc[it] + kq);
        }
    }
#pragma unroll
    for (int it = 0; it < 2; ++it) {
        int r = lrow + it * 64;
        As[0][kq + 0][r] = avr[it].x; As[0][kq + 1][r] = avr[it].y;
        As[0][kq + 2][r] = avr[it].z; As[0][kq + 3][r] = avr[it].w;
        Bs[0][kq + 0][r] = bvr[it].x; Bs[0][kq + 1][r] = bvr[it].y;
        Bs[0][kq + 2][r] = bvr[it].z; Bs[0][kq + 3][r] = bvr[it].w;
    }
    __syncthreads();

    for (int kt = 0; kt < 19; ++kt) {
        int cur = kt & 1;
        if (kt + 1 < 19) {
            int kb = (kt + 1) * 16 + kq;
#pragma unroll
            for (int it = 0; it < 2; ++it) {
                avr[it] = make_float4(0.f, 0.f, 0.f, 0.f);
                bvr[it] = make_float4(0.f, 0.f, 0.f, 0.f);
                if (kb < EE) {
                    avr[it] = *(const float4*)(emb + (size_t)tok[it] * EE + kb);
                    bvr[it] = *(const float4*)(wsrc[it] + kb);
                }
            }
        }
#pragma unroll
        for (int k = 0; k < 16; ++k) {
            ulonglong2 aA = *(const ulonglong2*)&As[cur][k][ty * 8];
            ulonglong2 aB = *(const ulonglong2*)&As[cur][k][ty * 8 + 4];
            float4 b0 = *(const float4*)&Bs[cur][k][tx * 8];
            float4 b1 = *(const float4*)&Bs[cur][k][tx * 8 + 4];
            u64t bd;
            bd = pack2(b0.x, b0.x); ffma2(acc[0][0], aA.x, bd); ffma2(acc[1][0], aA.y, bd); ffma2(acc[2][0], aB.x, bd); ffma2(acc[3][0], aB.y, bd);
            bd = pack2(b0.y, b0.y); ffma2(acc[0][1], aA.x, bd); ffma2(acc[1][1], aA.y, bd); ffma2(acc[2][1], aB.x, bd); ffma2(acc[3][1], aB.y, bd);
            bd = pack2(b0.z, b0.z); ffma2(acc[0][2], aA.x, bd); ffma2(acc[1][2], aA.y, bd); ffma2(acc[2][2], aB.x, bd); ffma2(acc[3][2], aB.y, bd);
            bd = pack2(b0.w, b0.w); ffma2(acc[0][3], aA.x, bd); ffma2(acc[1][3], aA.y, bd); ffma2(acc[2][3], aB.x, bd); ffma2(acc[3][3], aB.y, bd);
            bd = pack2(b1.x, b1.x); ffma2(acc[0][4], aA.x, bd); ffma2(acc[1][4], aA.y, bd); ffma2(acc[2][4], aB.x, bd); ffma2(acc[3][4], aB.y, bd);
            bd = pack2(b1.y, b1.y); ffma2(acc[0][5], aA.x, bd); ffma2(acc[1][5], aA.y, bd); ffma2(acc[2][5], aB.x, bd); ffma2(acc[3][5], aB.y, bd);
            bd = pack2(b1.z, b1.z); ffma2(acc[0][6], aA.x, bd); ffma2(acc[1][6], aA.y, bd); ffma2(acc[2][6], aB.x, bd); ffma2(acc[3][6], aB.y, bd);
            bd = pack2(b1.w, b1.w); ffma2(acc[0][7], aA.x, bd); ffma2(acc[1][7], aA.y, bd); ffma2(acc[2][7], aB.x, bd); ffma2(acc[3][7], aB.y, bd);
        }
        if (kt + 1 < 19) {
            int nxt = cur ^ 1;
#pragma unroll
            for (int it = 0; it < 2; ++it) {
                int r = lrow + it * 64;
                As[nxt][kq + 0][r] = avr[it].x; As[nxt][kq + 1][r] = avr[it].y;
                As[nxt][kq + 2][r] = avr[it].z; As[nxt][kq + 3][r] = avr[it].w;
                Bs[nxt][kq + 0][r] = bvr[it].x; Bs[nxt][kq + 1][r] = bvr[it].y;
                Bs[nxt][kq + 2][r] = bvr[it].z; Bs[nxt][kq + 3][r] = bvr[it].w;
            }
            __syncthreads();
        }
    }
    float bias[8];
#pragma unroll
    for (int j = 0; j < 8; ++j) {
        int n = n0 + tx * 8 + j;
        bias[j] = (n < 1024) ? bf[n] : bb[n - 1024];
    }
#pragma unroll
    for (int r = 0; r < 8; ++r) {
        int m = m0 + ty * 8 + r;
        int mp = r >> 1, hi = r & 1;
        float v[8];
#pragma unroll
        for (int j = 0; j < 8; ++j) {
            float2 p = unpack2(acc[mp][j]);
            v[j] = (hi ? p.y : p.x) + bias[j];
        }
        float* cp = g_xproj + (size_t)m * 2048 + n0 + tx * 8;
        *(float4*)cp       = make_float4(v[0], v[1], v[2], v[3]);
        *(float4*)(cp + 4) = make_float4(v[4], v[5], v[6], v[7]);
    }
}

// ---------------- persistent BiLSTM recurrence ----------------
__device__ __forceinline__ float sigf(float x) { return 1.f / (1.f + expf(-x)); }

// 128 blocks: dir(2) x unit-chunk(16, 16 units each) x batch-chunk(4, 16 rows each)
__global__ void __launch_bounds__(256, 1) k_lstm(const float* __restrict__ Whh_f,
                                                 const float* __restrict__ Whh_b) {
    extern __shared__ float sm[];
    float4* W4 = (float4*)sm;                 // [kc(64)][lu(16)][g(4)] = 64KB
    float4* h4 = (float4*)(sm + 16384);       // [kc(64)][lb(16)]       = 16KB
    float* xg  = sm + 16384 + 4096;           // [g(4)][bb(16)][u'(17)] = 4.25KB
    __shared__ unsigned sb_sh;                // flag base snapshot (replay-relative)

    int bx = blockIdx.x;
    int dir = bx >> 6;
    int rem = bx & 63;
    int uc = rem >> 2;
    int bc = rem & 3;
    int grp = dir * 4 + bc;
    int tid = threadIdx.x;
    int lu = tid >> 4;
    int lb = tid & 15;
    int U = uc * 16 + lu;
    int B0 = bc * 16;
    int b = B0 + lb;
    const float* Whh = dir ? Whh_b : Whh_f;

    int chunk = tid >> 2;
    int bb = chunk >> 2;
    int gg = chunk & 3;
    int tq = (tid & 3) * 4;

    // snapshot my own flag BEFORE my first write: all group flags are equal at
    // replay start (previous replay fully completed), so this is the group base.
    if (tid == 0) sb_sh = *(volatile unsigned*)&g_flag[(grp * 16 + uc) * 32];

    for (int i = tid; i < 64 * 64; i += 256) {
        int r = i >> 6;
        int kc = i & 63;
        int lur = r >> 2, g = r & 3;
        int grow = g * 256 + uc * 16 + lur;
        W4[(kc * 16 + lur) * 4 + g] = *(const float4*)(Whh + (size_t)grow * HH + kc * 4);
    }

    float c_st = 0.f;

    for (int s = 0; s < TT; ++s) {
        int t = dir ? (TT - 1 - s) : s;
        const float* gsrc = g_xproj + (size_t)(t * 64 + B0 + bb) * 2048
                            + dir * 1024 + gg * 256 + uc * 16 + tq;
        float4 gv = *(const float4*)gsrc;

        if (s > 0) {
            // distributed monotonic-flag barrier #s: release own flag, poll 16 peers
            __syncthreads();                       // all prior h-stores of this block done
            unsigned base = sb_sh;
            if (tid == 0)
                st_release(&g_flag[(grp * 16 + uc) * 32], base + (unsigned)s);
            if (tid < 16) {
                unsigned tgt = base + (unsigned)s;
                while ((int)(ld_acquire(&g_flag[(grp * 16 + tid) * 32]) - tgt) < 0) { }
            }
            __syncthreads();                       // acquire visible to all threads

            int tp = dir ? (t + 1) : (t - 1);
            const float* hp = g_hcat + ((size_t)(tp * 64 + B0)) * 512 + dir * 256;
#pragma unroll
            for (int i = 0; i < 4; ++i) {
                int idx = i * 256 + tid;
                int c4 = idx >> 4;
                int lbi = idx & 15;
                h4[c4 * 16 + lbi] = *(const float4*)(hp + lbi * 512 + c4 * 4);
            }
        }
        {
            int base2 = (gg * 16 + bb) * 17 + tq;
            xg[base2 + 0] = gv.x; xg[base2 + 1] = gv.y;
            xg[base2 + 2] = gv.z; xg[base2 + 3] = gv.w;
        }
        __syncthreads();

        float x_i = xg[(0 * 16 + lb) * 17 + lu];
        float x_f = xg[(1 * 16 + lb) * 17 + lu];
        float x_g = xg[(2 * 16 + lb) * 17 + lu];
        float x_o = xg[(3 * 16 + lb) * 17 + lu];

        u64t a_i = 0ull, a_f = 0ull, a_g = 0ull, a_o = 0ull;
        if (s > 0) {
#pragma unroll 4
            for (int kc = 0; kc < 64; ++kc) {
                ulonglong2 hv = *(const ulonglong2*)&h4[kc * 16 + lb];
                const ulonglong2* wr = (const ulonglong2*)&W4[(kc * 16 + lu) * 4];
                ulonglong2 wi = wr[0], wf = wr[1], wg = wr[2], wo = wr[3];
                ffma2(a_i, hv.x, wi.x); ffma2(a_i, hv.y, wi.y);
                ffma2(a_f, hv.x, wf.x); ffma2(a_f, hv.y, wf.y);
                ffma2(a_g, hv.x, wg.x); ffma2(a_g, hv.y, wg.y);
                ffma2(a_o, hv.x, wo.x); ffma2(a_o, hv.y, wo.y);
            }
        }
        float2 vi = unpack2(a_i), vf = unpack2(a_f), vg = unpack2(a_g), vo = unpack2(a_o);
        float pi = vi.x + vi.y + x_i;
        float pf = vf.x + vf.y + x_f;
        float pg = vg.x + vg.y + x_g;
        float po = vo.x + vo.y + x_o;
        c_st = sigf(pf) * c_st + sigf(pi) * tanhf(pg);
        float h = sigf(po) * tanhf(c_st);
        g_hcat[((size_t)(t * 64 + b)) * 512 + dir * 256 + U] = h;
    }
    // no final barrier needed: flags are monotonic; all flags end at base+255
    // (every block's last in-loop barrier writes it), so next replay's snapshot
    // is uniform. h-visibility to k_fc is guaranteed by the kernel boundary.
}

// ---------------- fc1 + relu + cls -> unary (fused, f32x2 m-paired) ----------------
__global__ void k_fc(const float* __restrict__ W1, const float* __restrict__ b1,
                     const float* __restrict__ Wc, const float* __restrict__ bcls) {
    extern __shared__ float sm[];
    float (*As)[68]  = (float(*)[68])sm;                    // [k][m] 16*68 = 1088 f
    float (*Bs)[132] = (float(*)[132])(sm + 1088);          // [k][n] 16*132 = 2112 f
    float* cls_sh  = sm + 1088 + 2112;                      // 17*128 = 2176 f
    float* clsb_sh = cls_sh + 2176;                         // 32 f
    float* inter   = clsb_sh + 32;                          // 64*132 = 8448 f

    int m0 = blockIdx.x * 64;
    int tid = threadIdx.x;
    int tm = tid >> 4, tn = tid & 15;
    int arow = tid >> 2, aq = (tid & 3) * 4;
    int brow = tid >> 1, bq = tid & 1;

    for (int i = tid; i < 17 * 128; i += 256) cls_sh[i] = Wc[i];
    if (tid < 17) clsb_sh[tid] = bcls[tid];

    u64t acc[2][8];
#pragma unroll
    for (int i = 0; i < 2; ++i)
#pragma unroll
        for (int j = 0; j < 8; ++j) acc[i][j] = 0ull;

    for (int kt = 0; kt < 32; ++kt) {
        int k0 = kt * 16;
        float4 av = *(const float4*)(g_hcat + (size_t)(m0 + arow) * 512 + k0 + aq);
        As[aq + 0][arow] = av.x;
        As[aq + 1][arow] = av.y;
        As[aq + 2][arow] = av.z;
        As[aq + 3][arow] = av.w;
#pragma unroll
        for (int q = 0; q < 2; ++q) {
            float4 bv = *(const float4*)(W1 + (size_t)brow * 512 + k0 + bq * 8 + q * 4);
            Bs[bq * 8 + q * 4 + 0][brow] = bv.x;
            Bs[bq * 8 + q * 4 + 1][brow] = bv.y;
            Bs[bq * 8 + q * 4 + 2][brow] = bv.z;
            Bs[bq * 8 + q * 4 + 3][brow] = bv.w;
        }
        __syncthreads();
#pragma unroll
        for (int k = 0; k < 16; ++k) {
            ulonglong2 aA = *(const ulonglong2*)&As[k][tm * 4];
            float4 b0 = *(const float4*)&Bs[k][tn * 8];
            float4 b1 = *(const float4*)&Bs[k][tn * 8 + 4];
            u64t bd;
            bd = pack2(b0.x, b0.x); ffma2(acc[0][0], aA.x, bd); ffma2(acc[1][0], aA.y, bd);
            bd = pack2(b0.y, b0.y); ffma2(acc[0][1], aA.x, bd); ffma2(acc[1][1], aA.y, bd);
            bd = pack2(b0.z, b0.z); ffma2(acc[0][2], aA.x, bd); ffma2(acc[1][2], aA.y, bd);
            bd = pack2(b0.w, b0.w); ffma2(acc[0][3], aA.x, bd); ffma2(acc[1][3], aA.y, bd);
            bd = pack2(b1.x, b1.x); ffma2(acc[0][4], aA.x, bd); ffma2(acc[1][4], aA.y, bd);
            bd = pack2(b1.y, b1.y); ffma2(acc[0][5], aA.x, bd); ffma2(acc[1][5], aA.y, bd);
            bd = pack2(b1.z, b1.z); ffma2(acc[0][6], aA.x, bd); ffma2(acc[1][6], aA.y, bd);
            bd = pack2(b1.w, b1.w); ffma2(acc[0][7], aA.x, bd); ffma2(acc[1][7], aA.y, bd);
        }
        __syncthreads();
    }
#pragma unroll
    for (int r = 0; r < 4; ++r) {
        int ml = tm * 4 + r;
        int mp = r >> 1, hi = r & 1;
#pragma unroll
        for (int j = 0; j < 8; ++j) {
            float2 p = unpack2(acc[mp][j]);
            int n = tn * 8 + j;
            float v = (hi ? p.y : p.x) + b1[n];
            inter[ml * 132 + n] = v > 0.f ? v : 0.f;
        }
    }
    __syncthreads();
    for (int o = tid; o < 64 * TL; o += 256) {
        int ml = o / TL, l = o - ml * TL;
        int m = m0 + ml;
        int t = m >> 6, bat = m & 63;
        float v;
        if (l < NUM_LABELS) {
            u64t s2 = 0ull;
            const ulonglong2* ip = (const ulonglong2*)(inter + ml * 132);
            const ulonglong2* cp = (const ulonglong2*)(cls_sh + l * 128);
#pragma unroll 8
            for (int k4 = 0; k4 < 32; ++k4) {
                ulonglong2 a = ip[k4], c = cp[k4];
                ffma2(s2, a.x, c.x);
                ffma2(s2, a.y, c.y);
            }
            float2 p = unpack2(s2);
            v = clsb_sh[l] + p.x + p.y;
        } else {
            v = LOW_POT;
        }
        g_unary[((size_t)bat * TT + t) * TL + l] = v;
    }
}

// ---------------- Viterbi: slim serial forward + parallel backpointer phase ----------------
__global__ void __launch_bounds__(128) k_viterbi(const float* __restrict__ trans,
                                                 float* __restrict__ out,
                                                 int score_off, int labels_off) {
    __shared__ __align__(16) float hist[257][20];   // hist[t] = score before step t
    __shared__ float T_sh[TL * TL];
    __shared__ unsigned char bp[256 * TL];
    __shared__ int s_last;
    int bIdx = blockIdx.x;
    int tid = threadIdx.x;
    int l = tid & 31;
    int wid = tid >> 5;

    for (int i = tid; i < TL * TL; i += 128) T_sh[i] = trans[i];
    if (tid < 20) hist[0][tid] = (tid == START_IDX) ? 0.f : LOW_POT;
    __syncthreads();

    if (wid == 0) {
        float trrow[TL];
#pragma unroll
        for (int p = 0; p < TL; ++p) trrow[p] = (l < TL) ? T_sh[l * TL + p] : 0.f;
        float tr_end = (l < TL) ? T_sh[END_IDX * TL + l] : 0.f;

        const float* ub = g_unary + (size_t)bIdx * TT * TL;
        float u_next  = (l < TL) ? ub[l] : LOW_POT;
        float u_next2 = (l < TL) ? ub[TL + l] : LOW_POT;
        float score = LOW_POT;

        for (int t = 0; t < TT; ++t) {
            float4 s0 = *(const float4*)&hist[t][0];
            float4 s1 = *(const float4*)&hist[t][4];
            float4 s2 = *(const float4*)&hist[t][8];
            float4 s3 = *(const float4*)&hist[t][12];
            float4 s4 = *(const float4*)&hist[t][16];

            float c0  = s0.x + trrow[0],  c1  = s0.y + trrow[1];
            float c2  = s0.z + trrow[2],  c3  = s0.w + trrow[3];
            float c4  = s1.x + trrow[4],  c5  = s1.y + trrow[5];
            float c6  = s1.z + trrow[6],  c7  = s1.w + trrow[7];
            float c8  = s2.x + trrow[8],  c9  = s2.y + trrow[9];
            float c10 = s2.z + trrow[10], c11 = s2.w + trrow[11];
            float c12 = s3.x + trrow[12], c13 = s3.y + trrow[13];
            float c14 = s3.z + trrow[14], c15 = s3.w + trrow[15];
            float c16 = s4.x + trrow[16], c17 = s4.y + trrow[17];
            float c18 = s4.z + trrow[18];

            float a0 = fmaxf(c0, c1),  a1 = fmaxf(c2, c3);
            float a2 = fmaxf(c4, c5),  a3 = fmaxf(c6, c7);
            float a4 = fmaxf(c8, c9),  a5 = fmaxf(c10, c11);
            float a6 = fmaxf(c12, c13), a7 = fmaxf(c14, c15);
            float a8 = fmaxf(c16, c17);
            float b0 = fmaxf(a0, a1), b1 = fmaxf(a2, a3);
            float b2 = fmaxf(a4, a5), b3 = fmaxf(a6, a7);
            float b4 = fmaxf(a8, c18);
            float d0 = fmaxf(b0, b1), d1 = fmaxf(b2, b3);
            float m  = fmaxf(fmaxf(d0, d1), b4);

            float u = u_next;
            u_next = u_next2;
            int tp = (t + 2 < TT) ? (t + 2) : (TT - 1);
            u_next2 = (l < TL) ? ub[tp * TL + l] : LOW_POT;

            score = m + u;
            if (l < TL) hist[t + 1][l] = score;
            __syncwarp();
        }

        float fin = (l < TL) ? (score + tr_end) : -3.4e38f;
        int idx = (l < TL) ? l : 31;
#pragma unroll
        for (int off = 16; off; off >>= 1) {
            float ov = __shfl_down_sync(0xffffffffu, fin, off);
            int   oi = __shfl_down_sync(0xffffffffu, idx, off);
            if (ov > fin || (ov == fin && oi < idx)) { fin = ov; idx = oi; }
        }
        if (l == 0) {
            s_last = idx;
            if (score_off >= 0) out[score_off + bIdx] = fin;
        }
    }
    __syncthreads();

    for (int i = tid; i < 255 * TL; i += 128) {
        int t = 1 + i / TL;
        int ll = i - (i / TL) * TL;
        const float* hp = &hist[t][0];
        const float* tr = &T_sh[ll * TL];
        float best = -3.4e38f; int bi = 0;
#pragma unroll
        for (int p = 0; p < TL; ++p) {
            float v = hp[p] + tr[p];
            if (v > best) { best = v; bi = p; }
        }
        bp[t * TL + ll] = (unsigned char)bi;
    }
    __syncthreads();

    if (tid == 0 && labels_off >= 0) {
        int lab = s_last;
        float* lo = out + labels_off + (size_t)bIdx * TT;
        lo[TT - 1] = (float)lab;
        for (int t = TT - 1; t >= 1; --t) {
            lab = bp[t * TL + lab];
            lo[t - 1] = (float)lab;
        }
    }
}

// ---------------- launch ----------------
extern "C" void kernel_launch(void* const* d_in, const int* in_sizes, int n_in,
                              void* d_out, int out_size) {
    const int*   x        = (const int*)d_in[0];
    const float* emb_tab  = (const float*)d_in[1];
    const float* W_ih_f   = (const float*)d_in[2];
    const float* W_hh_f   = (const float*)d_in[3];
    const float* b_f      = (const float*)d_in[4];
    const float* W_ih_b   = (const float*)d_in[5];
    const float* W_hh_b   = (const float*)d_in[6];
    const float* b_b      = (const float*)d_in[7];
    const float* fc1_W    = (const float*)d_in[8];
    const float* fc1_b    = (const float*)d_in[9];
    const float* cls_W    = (const float*)d_in[10];
    const float* cls_b    = (const float*)d_in[11];
    const float* trans    = (const float*)d_in[12];
    float* out = (float*)d_out;

    cudaFuncSetAttribute(k_lstm, cudaFuncAttributeMaxDynamicSharedMemorySize, 86272);
    cudaFuncSetAttribute(k_fc,   cudaFuncAttributeMaxDynamicSharedMemorySize, 57344);

    // ncu probe: capture window = launch index 3 -> k_lstm
    k_noop<<<1, 32>>>();
    k_noop<<<1, 32>>>();

    dim3 g1(2048 / 128, MTOT / 128);
    k_gemm_xproj<<<g1, 256>>>(x, emb_tab, W_ih_f, W_ih_b, b_f, b_b);

    k_lstm<<<NB_LSTM, 256, 86272>>>(W_hh_f, W_hh_b);

    k_fc<<<MTOT / 64, 256, 57344>>>(fc1_W, fc1_b, cls_W, cls_b);

    int score_off, labels_off;
    if (out_size >= BB + BB * TT) { score_off = 0; labels_off = BB; }
    else if (out_size == BB * TT) { score_off = -1; labels_off = 0; }
    else                          { score_off = 0; labels_off = -1; }
    k_viterbi<<<BB, 128>>>(trans, out, score_off, labels_off);
}

// round 17
// speedup vs baseline: 1.2741x; 1.0294x over previous
#include <cuda_runtime.h>
#include <cuda_bf16.h>
#include <math.h>

// ---------------- problem constants ----------------
#define BB 64
#define TT 256
#define EE 300
#define HH 256
#define INTER 128
#define NUM_LABELS 17
#define TL 19           // TOTAL_LABELS
#define START_IDX 17
#define END_IDX 18
#define LOW_POT -10000.0f

#define MTOT (BB*TT)            // 16384, m = t*64 + b
#define NB_LSTM 128             // persistent blocks (16 uc x 8 bc), both dirs per block

typedef unsigned long long u64t;

// packed fp32x2 FMA (sm_100+): d = a*b + d elementwise, exact IEEE per lane
__device__ __forceinline__ void ffma2(u64t& d, u64t a, u64t b) {
    asm("fma.rn.f32x2 %0, %1, %2, %0;" : "+l"(d) : "l"(a), "l"(b));
}
__device__ __forceinline__ u64t pack2(float lo, float hi) {
    u64t r; asm("mov.b64 %0, {%1,%2};" : "=l"(r) : "f"(lo), "f"(hi)); return r;
}
__device__ __forceinline__ float2 unpack2(u64t v) {
    float2 r; asm("mov.b64 {%0,%1}, %2;" : "=f"(r.x), "=f"(r.y) : "l"(v)); return r;
}

// scoped release/acquire for the distributed barrier
__device__ __forceinline__ void st_release(unsigned* p, unsigned v) {
    asm volatile("st.release.gpu.u32 [%0], %1;" :: "l"(p), "r"(v) : "memory");
}
__device__ __forceinline__ unsigned ld_acquire(const unsigned* p) {
    unsigned v;
    asm volatile("ld.acquire.gpu.u32 %0, [%1];" : "=r"(v) : "l"(p) : "memory");
    return v;
}
__device__ __forceinline__ void bar_sync(int id) {
    asm volatile("bar.sync %0, 128;" :: "r"(id) : "memory");
}

// ---------------- scratch (device globals; allocation-free rule) ----------------
__device__ float g_xproj[(size_t)MTOT * 2048];// [t][b][dir*1024 + g*256 + u]
__device__ float g_hcat[(size_t)MTOT * 512];  // [t][b][dir*256 + u]
__device__ float g_unary[BB * TT * TL];       // [b][t][l]
__device__ unsigned g_flag[16 * 16 * 32];     // [grp(dir*8+bc)][member(uc)] monotonic flags

// ---------------- ncu probe: put k_lstm at launch index 4 ----------------
__global__ void k_noop() {}

// ---------------- x_proj GEMM (fused embedding gather, double-buffered) ----------------
__global__ void __launch_bounds__(256) k_gemm_xproj(
        const int* __restrict__ x, const float* __restrict__ emb,
        const float* __restrict__ Wf, const float* __restrict__ Wb,
        const float* __restrict__ bf, const float* __restrict__ bb) {
    __shared__ float As[2][16][132];   // [buf][k][m] transposed
    __shared__ float Bs[2][16][132];   // [buf][k][n] transposed
    int tid = threadIdx.x;
    int n0 = blockIdx.x * 128;
    int m0 = blockIdx.y * 128;
    int tx = tid & 15, ty = tid >> 4;
    int lrow = tid >> 2;          // 0..63
    int kq = (tid & 3) * 4;       // 0,4,8,12

    int tok[2]; const float* wsrc[2];
#pragma unroll
    for (int it = 0; it < 2; ++it) {
        int m = m0 + lrow + it * 64;
        tok[it] = x[(m & 63) * TT + (m >> 6)];
        int ng = n0 + lrow + it * 64;
        wsrc[it] = (ng < 1024) ? (Wf + (size_t)ng * EE) : (Wb + (size_t)(ng - 1024) * EE);
    }

    u64t acc[4][8];
#pragma unroll
    for (int i = 0; i < 4; ++i)
#pragma unroll
        for (int j = 0; j < 8; ++j) acc[i][j] = 0ull;

    float4 avr[2], bvr[2];
#pragma unroll
    for (int it = 0; it < 2; ++it) {
        avr[it] = make_float4(0.f, 0.f, 0.f, 0.f);
        bvr[it] = make_float4(0.f, 0.f, 0.f, 0.f);
        if (kq < EE) {
            avr[it] = *(const float4*)(emb + (size_t)tok[it] * EE + kq);
            bvr[it] = *(const float4*)(wsrc[it] + kq);
        }
    }
#pragma unroll
    for (int it = 0; it < 2; ++it) {
        int r = lrow + it * 64;
        As[0][kq + 0][r] = avr[it].x; As[0][kq + 1][r] = avr[it].y;
        As[0][kq + 2][r] = avr[it].z; As[0][kq + 3][r] = avr[it].w;
        Bs[0][kq + 0][r] = bvr[it].x; Bs[0][kq + 1][r] = bvr[it].y;
        Bs[0][kq + 2][r] = bvr[it].z; Bs[0][kq + 3][r] = bvr[it].w;
    }
    __syncthreads();

    for (int kt = 0; kt < 19; ++kt) {
        int cur = kt & 1;
        if (kt + 1 < 19) {
            int kb = (kt + 1) * 16 + kq;
#pragma unroll
            for (int it = 0; it < 2; ++it) {
                avr[it] = make_float4(0.f, 0.f, 0.f, 0.f);
                bvr[it] = make_float4(0.f, 0.f, 0.f, 0.f);
                if (kb < EE) {
                    avr[it] = *(const float4*)(emb + (size_t)tok[it] * EE + kb);
                    bvr[it] = *(const float4*)(wsrc[it] + kb);
                }
            }
        }
#pragma unroll
        for (int k = 0; k < 16; ++k) {
            ulonglong2 aA = *(const ulonglong2*)&As[cur][k][ty * 8];
            ulonglong2 aB = *(const ulonglong2*)&As[cur][k][ty * 8 + 4];
            float4 b0 = *(const float4*)&Bs[cur][k][tx * 8];
            float4 b1 = *(const float4*)&Bs[cur][k][tx * 8 + 4];
            u64t bd;
            bd = pack2(b0.x, b0.x); ffma2(acc[0][0], aA.x, bd); ffma2(acc[1][0], aA.y, bd); ffma2(acc[2][0], aB.x, bd); ffma2(acc[3][0], aB.y, bd);
            bd = pack2(b0.y, b0.y); ffma2(acc[0][1], aA.x, bd); ffma2(acc[1][1], aA.y, bd); ffma2(acc[2][1], aB.x, bd); ffma2(acc[3][1], aB.y, bd);
            bd = pack2(b0.z, b0.z); ffma2(acc[0][2], aA.x, bd); ffma2(acc[1][2], aA.y, bd); ffma2(acc[2][2], aB.x, bd); ffma2(acc[3][2], aB.y, bd);
            bd = pack2(b0.w, b0.w); ffma2(acc[0][3], aA.x, bd); ffma2(acc[1][3], aA.y, bd); ffma2(acc[2][3], aB.x, bd); ffma2(acc[3][3], aB.y, bd);
            bd = pack2(b1.x, b1.x); ffma2(acc[0][4], aA.x, bd); ffma2(acc[1][4], aA.y, bd); ffma2(acc[2][4], aB.x, bd); ffma2(acc[3][4], aB.y, bd);
            bd = pack2(b1.y, b1.y); ffma2(acc[0][5], aA.x, bd); ffma2(acc[1][5], aA.y, bd); ffma2(acc[2][5], aB.x, bd); ffma2(acc[3][5], aB.y, bd);
            bd = pack2(b1.z, b1.z); ffma2(acc[0][6], aA.x, bd); ffma2(acc[1][6], aA.y, bd); ffma2(acc[2][6], aB.x, bd); ffma2(acc[3][6], aB.y, bd);
            bd = pack2(b1.w, b1.w); ffma2(acc[0][7], aA.x, bd); ffma2(acc[1][7], aA.y, bd); ffma2(acc[2][7], aB.x, bd); ffma2(acc[3][7], aB.y, bd);
        }
        if (kt + 1 < 19) {
            int nxt = cur ^ 1;
#pragma unroll
            for (int it = 0; it < 2; ++it) {
                int r = lrow + it * 64;
                As[nxt][kq + 0][r] = avr[it].x; As[nxt][kq + 1][r] = avr[it].y;
                As[nxt][kq + 2][r] = avr[it].z; As[nxt][kq + 3][r] = avr[it].w;
                Bs[nxt][kq + 0][r] = bvr[it].x; Bs[nxt][kq + 1][r] = bvr[it].y;
                Bs[nxt][kq + 2][r] = bvr[it].z; Bs[nxt][kq + 3][r] = bvr[it].w;
            }
            __syncthreads();
        }
    }
    float bias[8];
#pragma unroll
    for (int j = 0; j < 8; ++j) {
        int n = n0 + tx * 8 + j;
        bias[j] = (n < 1024) ? bf[n] : bb[n - 1024];
    }
#pragma unroll
    for (int r = 0; r < 8; ++r) {
        int m = m0 + ty * 8 + r;
        int mp = r >> 1, hi = r & 1;
        float v[8];
#pragma unroll
        for (int j = 0; j < 8; ++j) {
            float2 p = unpack2(acc[mp][j]);
            v[j] = (hi ? p.y : p.x) + bias[j];
        }
        float* cp = g_xproj + (size_t)m * 2048 + n0 + tx * 8;
        *(float4*)cp       = make_float4(v[0], v[1], v[2], v[3]);
        *(float4*)(cp + 4) = make_float4(v[4], v[5], v[6], v[7]);
    }
}

// ---------------- persistent BiLSTM: both directions per block ----------------
// 128 blocks = uc(16, 16 units) x bc(8, 8 batch rows). Threads: tid<128 -> fwd,
// tid>=128 -> bwd. Halves sync via named barriers (1/2) + per-dir flag groups,
// so when one chain stalls on its inter-block barrier, the sibling chain's
// warps keep the SMSPs busy.
__device__ __forceinline__ float sigf(float x) { return 1.f / (1.f + expf(-x)); }

// dynamic smem layout (floats)
#define SM_WF  0
#define SM_WB  16384
#define SM_HF  32768
#define SM_HB  34816
#define SM_XGF 36864
#define SM_XGB 37408
#define SM_LSTM_BYTES (37952 * 4)

__global__ void __launch_bounds__(256, 1) k_lstm(const float* __restrict__ Whh_f,
                                                 const float* __restrict__ Whh_b) {
    extern __shared__ float sm[];
    __shared__ unsigned sb_sh[2];
    int bx = blockIdx.x;
    int uc = bx >> 3;            // 0..15
    int bc = bx & 7;             // 0..7
    int tid = threadIdx.x;
    int dirh = tid >> 7;         // 0 fwd, 1 bwd
    int ht = tid & 127;
    int lu = ht >> 3;            // 0..15
    int lb = ht & 7;             // 0..7
    int U = uc * 16 + lu;
    int B0 = bc * 8;
    int b = B0 + lb;
    int grp = dirh * 8 + bc;     // 16 groups of 16 members
    int barid = 1 + dirh;
    const float* Whh = dirh ? Whh_b : Whh_f;
    float4* W4 = (float4*)(sm + (dirh ? SM_WB : SM_WF));
    float4* h4 = (float4*)(sm + (dirh ? SM_HB : SM_HF));
    float*  xg = sm + (dirh ? SM_XGB : SM_XGF);

    // base snapshot BEFORE any flag write (all group flags equal at replay start)
    if (ht == 0) sb_sh[dirh] = *(volatile unsigned*)&g_flag[(grp * 16 + uc) * 32];

    // each half loads its own W slice: rows {g*256 + uc*16 + lur}
    for (int i = ht; i < 64 * 64; i += 128) {
        int r = i >> 6;
        int kc = i & 63;
        int lur = r >> 2, g = r & 3;
        int grow = g * 256 + uc * 16 + lur;
        W4[(kc * 16 + lur) * 4 + g] = *(const float4*)(Whh + (size_t)grow * HH + kc * 4);
    }
    __syncthreads();   // W + sb_sh visible to whole block

    int chunk = ht >> 2;          // 0..31
    int bb = chunk >> 2;          // 0..7
    int gg = chunk & 3;           // 0..3
    int tq = (ht & 3) * 4;        // 0,4,8,12

    float c_st = 0.f;

    for (int s = 0; s < TT; ++s) {
        int t = dirh ? (TT - 1 - s) : s;
        // coalesced gate prefetch (16B/thread), latency hides behind barrier
        const float* gsrc = g_xproj + (size_t)(t * 64 + B0 + bb) * 2048
                            + dirh * 1024 + gg * 256 + uc * 16 + tq;
        float4 gv = *(const float4*)gsrc;

        if (s > 0) {
            bar_sync(barid);                       // own half's h-stores done
            unsigned base = sb_sh[dirh];
            if (ht == 0)
                st_release(&g_flag[(grp * 16 + uc) * 32], base + (unsigned)s);
            if (ht < 16) {
                unsigned tgt = base + (unsigned)s;
                while ((int)(ld_acquire(&g_flag[(grp * 16 + ht) * 32]) - tgt) < 0) { }
            }
            bar_sync(barid);                       // acquire visible to half
            int tp = dirh ? (t + 1) : (t - 1);
            const float* hp = g_hcat + ((size_t)(tp * 64 + B0)) * 512 + dirh * 256;
#pragma unroll
            for (int i = 0; i < 4; ++i) {
                int idx = i * 128 + ht;
                int c4 = idx >> 3;
                int lbi = idx & 7;
                h4[c4 * 8 + lbi] = *(const float4*)(hp + lbi * 512 + c4 * 4);
            }
        }
        {
            int base2 = (gg * 8 + bb) * 17 + tq;
            xg[base2 + 0] = gv.x; xg[base2 + 1] = gv.y;
            xg[base2 + 2] = gv.z; xg[base2 + 3] = gv.w;
        }
        bar_sync(barid);

        float x_i = xg[(0 * 8 + lb) * 17 + lu];
        float x_f = xg[(1 * 8 + lb) * 17 + lu];
        float x_g = xg[(2 * 8 + lb) * 17 + lu];
        float x_o = xg[(3 * 8 + lb) * 17 + lu];

        u64t a_i = 0ull, a_f = 0ull, a_g = 0ull, a_o = 0ull;
        if (s > 0) {
#pragma unroll 4
            for (int kc = 0; kc < 64; ++kc) {
                ulonglong2 hv = *(const ulonglong2*)&h4[kc * 8 + lb];
                const ulonglong2* wr = (const ulonglong2*)&W4[(kc * 16 + lu) * 4];
                ulonglong2 wi = wr[0], wf = wr[1], wg = wr[2], wo = wr[3];
                ffma2(a_i, hv.x, wi.x); ffma2(a_i, hv.y, wi.y);
                ffma2(a_f, hv.x, wf.x); ffma2(a_f, hv.y, wf.y);
                ffma2(a_g, hv.x, wg.x); ffma2(a_g, hv.y, wg.y);
                ffma2(a_o, hv.x, wo.x); ffma2(a_o, hv.y, wo.y);
            }
        }
        float2 vi = unpack2(a_i), vf = unpack2(a_f), vg = unpack2(a_g), vo = unpack2(a_o);
        float pi = vi.x + vi.y + x_i;
        float pf = vf.x + vf.y + x_f;
        float pg = vg.x + vg.y + x_g;
        float po = vo.x + vo.y + x_o;
        c_st = sigf(pf) * c_st + sigf(pi) * tanhf(pg);
        float h = sigf(po) * tanhf(c_st);
        g_hcat[((size_t)(t * 64 + b)) * 512 + dirh * 256 + U] = h;
    }
    // no final barrier: flags are monotonic (all end at base+255); kernel
    // boundary orders h stores for k_fc.
}

// ---------------- fc1 + relu + cls -> unary (fused, f32x2 m-paired) ----------------
__global__ void k_fc(const float* __restrict__ W1, const float* __restrict__ b1,
                     const float* __restrict__ Wc, const float* __restrict__ bcls) {
    extern __shared__ float sm[];
    float (*As)[68]  = (float(*)[68])sm;                    // [k][m] 16*68 = 1088 f
    float (*Bs)[132] = (float(*)[132])(sm + 1088);          // [k][n] 16*132 = 2112 f
    float* cls_sh  = sm + 1088 + 2112;                      // 17*128 = 2176 f
    float* clsb_sh = cls_sh + 2176;                         // 32 f
    float* inter   = clsb_sh + 32;                          // 64*132 = 8448 f

    int m0 = blockIdx.x * 64;
    int tid = threadIdx.x;
    int tm = tid >> 4, tn = tid & 15;
    int arow = tid >> 2, aq = (tid & 3) * 4;
    int brow = tid >> 1, bq = tid & 1;

    for (int i = tid; i < 17 * 128; i += 256) cls_sh[i] = Wc[i];
    if (tid < 17) clsb_sh[tid] = bcls[tid];

    u64t acc[2][8];
#pragma unroll
    for (int i = 0; i < 2; ++i)
#pragma unroll
        for (int j = 0; j < 8; ++j) acc[i][j] = 0ull;

    for (int kt = 0; kt < 32; ++kt) {
        int k0 = kt * 16;
        float4 av = *(const float4*)(g_hcat + (size_t)(m0 + arow) * 512 + k0 + aq);
        As[aq + 0][arow] = av.x;
        As[aq + 1][arow] = av.y;
        As[aq + 2][arow] = av.z;
        As[aq + 3][arow] = av.w;
#pragma unroll
        for (int q = 0; q < 2; ++q) {
            float4 bv = *(const float4*)(W1 + (size_t)brow * 512 + k0 + bq * 8 + q * 4);
            Bs[bq * 8 + q * 4 + 0][brow] = bv.x;
            Bs[bq * 8 + q * 4 + 1][brow] = bv.y;
            Bs[bq * 8 + q * 4 + 2][brow] = bv.z;
            Bs[bq * 8 + q * 4 + 3][brow] = bv.w;
        }
        __syncthreads();
#pragma unroll
        for (int k = 0; k < 16; ++k) {
            ulonglong2 aA = *(const ulonglong2*)&As[k][tm * 4];
            float4 b0 = *(const float4*)&Bs[k][tn * 8];
            float4 b1 = *(const float4*)&Bs[k][tn * 8 + 4];
            u64t bd;
            bd = pack2(b0.x, b0.x); ffma2(acc[0][0], aA.x, bd); ffma2(acc[1][0], aA.y, bd);
            bd = pack2(b0.y, b0.y); ffma2(acc[0][1], aA.x, bd); ffma2(acc[1][1], aA.y, bd);
            bd = pack2(b0.z, b0.z); ffma2(acc[0][2], aA.x, bd); ffma2(acc[1][2], aA.y, bd);
            bd = pack2(b0.w, b0.w); ffma2(acc[0][3], aA.x, bd); ffma2(acc[1][3], aA.y, bd);
            bd = pack2(b1.x, b1.x); ffma2(acc[0][4], aA.x, bd); ffma2(acc[1][4], aA.y, bd);
            bd = pack2(b1.y, b1.y); ffma2(acc[0][5], aA.x, bd); ffma2(acc[1][5], aA.y, bd);
            bd = pack2(b1.z, b1.z); ffma2(acc[0][6], aA.x, bd); ffma2(acc[1][6], aA.y, bd);
            bd = pack2(b1.w, b1.w); ffma2(acc[0][7], aA.x, bd); ffma2(acc[1][7], aA.y, bd);
        }
        __syncthreads();
    }
#pragma unroll
    for (int r = 0; r < 4; ++r) {
        int ml = tm * 4 + r;
        int mp = r >> 1, hi = r & 1;
#pragma unroll
        for (int j = 0; j < 8; ++j) {
            float2 p = unpack2(acc[mp][j]);
            int n = tn * 8 + j;
            float v = (hi ? p.y : p.x) + b1[n];
            inter[ml * 132 + n] = v > 0.f ? v : 0.f;
        }
    }
    __syncthreads();
    for (int o = tid; o < 64 * TL; o += 256) {
        int ml = o / TL, l = o - ml * TL;
        int m = m0 + ml;
        int t = m >> 6, bat = m & 63;
        float v;
        if (l < NUM_LABELS) {
            u64t s2 = 0ull;
            const ulonglong2* ip = (const ulonglong2*)(inter + ml * 132);
            const ulonglong2* cp = (const ulonglong2*)(cls_sh + l * 128);
#pragma unroll 8
            for (int k4 = 0; k4 < 32; ++k4) {
                ulonglong2 a = ip[k4], c = cp[k4];
                ffma2(s2, a.x, c.x);
                ffma2(s2, a.y, c.y);
            }
            float2 p = unpack2(s2);
            v = clsb_sh[l] + p.x + p.y;
        } else {
            v = LOW_POT;
        }
        g_unary[((size_t)bat * TT + t) * TL + l] = v;
    }
}

// ---------------- Viterbi: slim serial forward + parallel backpointer phase ----------------
__global__ void __launch_bounds__(128) k_viterbi(const float* __restrict__ trans,
                                                 float* __restrict__ out,
                                                 int score_off, int labels_off) {
    __shared__ __align__(16) float hist[257][20];
    __shared__ float T_sh[TL * TL];
    __shared__ unsigned char bp[256 * TL];
    __shared__ int s_last;
    int bIdx = blockIdx.x;
    int tid = threadIdx.x;
    int l = tid & 31;
    int wid = tid >> 5;

    for (int i = tid; i < TL * TL; i += 128) T_sh[i] = trans[i];
    if (tid < 20) hist[0][tid] = (tid == START_IDX) ? 0.f : LOW_POT;
    __syncthreads();

    if (wid == 0) {
        float trrow[TL];
#pragma unroll
        for (int p = 0; p < TL; ++p) trrow[p] = (l < TL) ? T_sh[l * TL + p] : 0.f;
        float tr_end = (l < TL) ? T_sh[END_IDX * TL + l] : 0.f;

        const float* ub = g_unary + (size_t)bIdx * TT * TL;
        float u_next  = (l < TL) ? ub[l] : LOW_POT;
        float u_next2 = (l < TL) ? ub[TL + l] : LOW_POT;
        float score = LOW_POT;

        for (int t = 0; t < TT; ++t) {
            float4 s0 = *(const float4*)&hist[t][0];
            float4 s1 = *(const float4*)&hist[t][4];
            float4 s2 = *(const float4*)&hist[t][8];
            float4 s3 = *(const float4*)&hist[t][12];
            float4 s4 = *(const float4*)&hist[t][16];

            float c0  = s0.x + trrow[0],  c1  = s0.y + trrow[1];
            float c2  = s0.z + trrow[2],  c3  = s0.w + trrow[3];
            float c4  = s1.x + trrow[4],  c5  = s1.y + trrow[5];
            float c6  = s1.z + trrow[6],  c7  = s1.w + trrow[7];
            float c8  = s2.x + trrow[8],  c9  = s2.y + trrow[9];
            float c10 = s2.z + trrow[10], c11 = s2.w + trrow[11];
            float c12 = s3.x + trrow[12], c13 = s3.y + trrow[13];
            float c14 = s3.z + trrow[14], c15 = s3.w + trrow[15];
            float c16 = s4.x + trrow[16], c17 = s4.y + trrow[17];
            float c18 = s4.z + trrow[18];

            float a0 = fmaxf(c0, c1),  a1 = fmaxf(c2, c3);
            float a2 = fmaxf(c4, c5),  a3 = fmaxf(c6, c7);
            float a4 = fmaxf(c8, c9),  a5 = fmaxf(c10, c11);
            float a6 = fmaxf(c12, c13), a7 = fmaxf(c14, c15);
            float a8 = fmaxf(c16, c17);
            float b0 = fmaxf(a0, a1), b1 = fmaxf(a2, a3);
            float b2 = fmaxf(a4, a5), b3 = fmaxf(a6, a7);
            float b4 = fmaxf(a8, c18);
            float d0 = fmaxf(b0, b1), d1 = fmaxf(b2, b3);
            float m  = fmaxf(fmaxf(d0, d1), b4);

            float u = u_next;
            u_next = u_next2;
            int tp = (t + 2 < TT) ? (t + 2) : (TT - 1);
            u_next2 = (l < TL) ? ub[tp * TL + l] : LOW_POT;

            score = m + u;
            if (l < TL) hist[t + 1][l] = score;
            __syncwarp();
        }

        float fin = (l < TL) ? (score + tr_end) : -3.4e38f;
        int idx = (l < TL) ? l : 31;
#pragma unroll
        for (int off = 16; off; off >>= 1) {
            float ov = __shfl_down_sync(0xffffffffu, fin, off);
            int   oi = __shfl_down_sync(0xffffffffu, idx, off);
            if (ov > fin || (ov == fin && oi < idx)) { fin = ov; idx = oi; }
        }
        if (l == 0) {
            s_last = idx;
            if (score_off >= 0) out[score_off + bIdx] = fin;
        }
    }
    __syncthreads();

    for (int i = tid; i < 255 * TL; i += 128) {
        int t = 1 + i / TL;
        int ll = i - (i / TL) * TL;
        const float* hp = &hist[t][0];
        const float* tr = &T_sh[ll * TL];
        float best = -3.4e38f; int bi = 0;
#pragma unroll
        for (int p = 0; p < TL; ++p) {
            float v = hp[p] + tr[p];
            if (v > best) { best = v; bi = p; }
        }
        bp[t * TL + ll] = (unsigned char)bi;
    }
    __syncthreads();

    if (tid == 0 && labels_off >= 0) {
        int lab = s_last;
        float* lo = out + labels_off + (size_t)bIdx * TT;
        lo[TT - 1] = (float)lab;
        for (int t = TT - 1; t >= 1; --t) {
            lab = bp[t * TL + lab];
            lo[t - 1] = (float)lab;
        }
    }
}

// ---------------- launch ----------------
extern "C" void kernel_launch(void* const* d_in, const int* in_sizes, int n_in,
                              void* d_out, int out_size) {
    const int*   x        = (const int*)d_in[0];
    const float* emb_tab  = (const float*)d_in[1];
    const float* W_ih_f   = (const float*)d_in[2];
    const float* W_hh_f   = (const float*)d_in[3];
    const float* b_f      = (const float*)d_in[4];
    const float* W_ih_b   = (const float*)d_in[5];
    const float* W_hh_b   = (const float*)d_in[6];
    const float* b_b      = (const float*)d_in[7];
    const float* fc1_W    = (const float*)d_in[8];
    const float* fc1_b    = (const float*)d_in[9];
    const float* cls_W    = (const float*)d_in[10];
    const float* cls_b    = (const float*)d_in[11];
    const float* trans    = (const float*)d_in[12];
    float* out = (float*)d_out;

    cudaFuncSetAttribute(k_lstm, cudaFuncAttributeMaxDynamicSharedMemorySize, SM_LSTM_BYTES);
    cudaFuncSetAttribute(k_fc,   cudaFuncAttributeMaxDynamicSharedMemorySize, 57344);

    // ncu probe: capture window = 4th launch -> k_lstm
    k_noop<<<1, 32>>>();
    k_noop<<<1, 32>>>();

    dim3 g1(2048 / 128, MTOT / 128);
    k_gemm_xproj<<<g1, 256>>>(x, emb_tab, W_ih_f, W_ih_b, b_f, b_b);

    k_lstm<<<NB_LSTM, 256, SM_LSTM_BYTES>>>(W_hh_f, W_hh_b);

    k_fc<<<MTOT / 64, 256, 57344>>>(fc1_W, fc1_b, cls_W, cls_b);

    int score_off, labels_off;
    if (out_size >= BB + BB * TT) { score_off = 0; labels_off = BB; }
    else if (out_size == BB * TT) { score_off = -1; labels_off = 0; }
    else                          { score_off = 0; labels_off = -1; }
    k_viterbi<<<BB, 128>>>(trans, out, score_off, labels_off);
}